// round 4
// baseline (speedup 1.0000x reference)
#include <cuda_runtime.h>

// ---------------------------------------------------------------------------
// Fused MultiHeadAttention: B=4, S=2048, D=1024, H=16, dk=64  (all fp32)
//   qh = q@Wq^T + bq  (head layout)   kh, vh likewise
//   ctx = softmax(qh kh^T / 8 + mask) vh        (flash-style)
//   out = concat(ctx) @ Wo^T + bo
// ---------------------------------------------------------------------------

#define BB 4
#define SS 2048
#define DM 1024
#define HH 16
#define DK 64
#define MROWS (BB * SS)   // 8192

// scratch (allocation-free rule: __device__ globals)
__device__ float g_qh[BB * HH * SS * DK];
__device__ float g_kh[BB * HH * SS * DK];
__device__ float g_vh[BB * HH * SS * DK];
__device__ float g_ct[BB * SS * DM];

// ---------------------------------------------------------------------------
// GEMM:  Y[m,e] = sum_d X[m,d] * W[e,d] + bias[e]
// Tiles: 64(M) x 64(N) x 16(K), 256 threads, 4x4 per-thread micro-tile.
// HEAD_OUT: write Y into [B,H,S,DK] layout (tile width 64 == DK, so the
//           whole N-tile belongs to head h = blockIdx.y).
// ---------------------------------------------------------------------------
template <bool HEAD_OUT>
__global__ void __launch_bounds__(256, 4) gemm_bias_kernel(
    const float* __restrict__ X,     // [MROWS, DM]
    const float* __restrict__ W,     // [DM(e), DM(d)]
    const float* __restrict__ bias,  // [DM]
    float* __restrict__ Y)
{
    __shared__ float As[16][65];   // [k][m]
    __shared__ float Bs[16][65];   // [k][e]

    const int tid = threadIdx.x;
    const int tx = tid & 15;       // N group
    const int ty = tid >> 4;       // M group
    const int m0 = blockIdx.x * 64;
    const int e0 = blockIdx.y * 64;

    // cooperative load mapping: each thread loads one float4 of X and W per step
    const int lr = tid >> 2;             // 0..63 (row within tile)
    const int lk = (tid & 3) << 2;       // 0,4,8,12 (k within tile)

    const float* xptr = X + (size_t)(m0 + lr) * DM + lk;
    const float* wptr = W + (size_t)(e0 + lr) * DM + lk;

    float acc[4][4] = {};

    for (int k0 = 0; k0 < DM; k0 += 16) {
        float4 xa = *(const float4*)(xptr + k0);
        float4 wb = *(const float4*)(wptr + k0);
        As[lk + 0][lr] = xa.x; As[lk + 1][lr] = xa.y;
        As[lk + 2][lr] = xa.z; As[lk + 3][lr] = xa.w;
        Bs[lk + 0][lr] = wb.x; Bs[lk + 1][lr] = wb.y;
        Bs[lk + 2][lr] = wb.z; Bs[lk + 3][lr] = wb.w;
        __syncthreads();

        #pragma unroll
        for (int kk = 0; kk < 16; kk++) {
            float a[4], b[4];
            #pragma unroll
            for (int i = 0; i < 4; i++) a[i] = As[kk][ty * 4 + i];
            #pragma unroll
            for (int j = 0; j < 4; j++) b[j] = Bs[kk][tx * 4 + j];
            #pragma unroll
            for (int i = 0; i < 4; i++)
                #pragma unroll
                for (int j = 0; j < 4; j++)
                    acc[i][j] = fmaf(a[i], b[j], acc[i][j]);
        }
        __syncthreads();
    }

    // epilogue
    const float4 bv = *(const float4*)(bias + e0 + tx * 4);
    #pragma unroll
    for (int i = 0; i < 4; i++) {
        const int m = m0 + ty * 4 + i;
        float4 r;
        r.x = acc[i][0] + bv.x;
        r.y = acc[i][1] + bv.y;
        r.z = acc[i][2] + bv.z;
        r.w = acc[i][3] + bv.w;
        if (HEAD_OUT) {
            const int b = m >> 11;            // m / S
            const int s = m & (SS - 1);
            const int h = e0 >> 6;            // tile width == DK
            float* dst = Y + ((size_t)((b * HH + h) * SS + s)) * DK + tx * 4;
            *(float4*)dst = r;
        } else {
            float* dst = Y + (size_t)m * DM + e0 + tx * 4;
            *(float4*)dst = r;
        }
    }
}

// ---------------------------------------------------------------------------
// Flash attention (fp32, online softmax).
// Grid: (S/64 q-tiles, B*H). Block: 256 threads (16x16), 4x4 micro-tiles.
// smem: Qs[64][65] (Q, pre-scaled by 1/8), KPs[64][65] (K tile, reused as P),
//       Vs[64][64].
// ---------------------------------------------------------------------------
__global__ void __launch_bounds__(256, 2) flash_kernel(
    const int* __restrict__ mask,       // [B,S,S]
    float* __restrict__ out_concat)     // [B,S,DM] (h*64+d layout)
{
    extern __shared__ float sm[];
    float* Qs  = sm;                 // 64*65
    float* KPs = sm + 64 * 65;       // 64*65
    float* Vs  = sm + 2 * 64 * 65;   // 64*64

    const int tid = threadIdx.x;
    const int tx = tid & 15;
    const int ty = tid >> 4;
    const int bh = blockIdx.y;           // b*16 + h
    const int b  = bh >> 4;
    const int h  = bh & 15;
    const int q0 = blockIdx.x * 64;

    const float* Qg = g_qh + ((size_t)bh * SS + q0) * DK;
    const float* Kg = g_kh + (size_t)bh * SS * DK;
    const float* Vg = g_vh + (size_t)bh * SS * DK;
    const int*   Mg = mask + (size_t)b * SS * SS + (size_t)q0 * SS;

    // load Q tile (scaled by 1/sqrt(dk) = 0.125)
    #pragma unroll
    for (int t = 0; t < 4; t++) {
        const int lin = tid + t * 256;
        const int r = lin >> 4;
        const int c4 = (lin & 15) << 2;
        float4 qv = *(const float4*)(Qg + r * DK + c4);
        Qs[r * 65 + c4 + 0] = qv.x * 0.125f;
        Qs[r * 65 + c4 + 1] = qv.y * 0.125f;
        Qs[r * 65 + c4 + 2] = qv.z * 0.125f;
        Qs[r * 65 + c4 + 3] = qv.w * 0.125f;
    }

    float m_i[4] = {-1e30f, -1e30f, -1e30f, -1e30f};
    float l_i[4] = {0.f, 0.f, 0.f, 0.f};
    float o[4][4] = {};

    for (int kt = 0; kt < SS / 64; kt++) {
        __syncthreads();   // previous P/V consumers done (and Q ready on iter 0)

        // load K, V tiles
        const float* kp = Kg + (size_t)kt * 64 * DK;
        const float* vp = Vg + (size_t)kt * 64 * DK;
        #pragma unroll
        for (int t = 0; t < 4; t++) {
            const int lin = tid + t * 256;
            const int r = lin >> 4;
            const int c4 = (lin & 15) << 2;
            float4 kv = *(const float4*)(kp + r * DK + c4);
            KPs[r * 65 + c4 + 0] = kv.x;
            KPs[r * 65 + c4 + 1] = kv.y;
            KPs[r * 65 + c4 + 2] = kv.z;
            KPs[r * 65 + c4 + 3] = kv.w;
            float4 vv = *(const float4*)(vp + r * DK + c4);
            *(float4*)&Vs[r * 64 + c4] = vv;
        }
        __syncthreads();

        // scores: s[i][j] = Qrow . Kcol
        float s[4][4] = {};
        #pragma unroll 16
        for (int kk = 0; kk < DK; kk++) {
            float a[4], bb[4];
            #pragma unroll
            for (int i = 0; i < 4; i++) a[i] = Qs[(ty * 4 + i) * 65 + kk];
            #pragma unroll
            for (int j = 0; j < 4; j++) bb[j] = KPs[(tx * 4 + j) * 65 + kk];
            #pragma unroll
            for (int i = 0; i < 4; i++)
                #pragma unroll
                for (int j = 0; j < 4; j++)
                    s[i][j] = fmaf(a[i], bb[j], s[i][j]);
        }

        // mask
        #pragma unroll
        for (int i = 0; i < 4; i++) {
            const int4 mm = *(const int4*)(Mg + (size_t)(ty * 4 + i) * SS + kt * 64 + tx * 4);
            if (mm.x == 0) s[i][0] = -1e9f;
            if (mm.y == 0) s[i][1] = -1e9f;
            if (mm.z == 0) s[i][2] = -1e9f;
            if (mm.w == 0) s[i][3] = -1e9f;
        }

        // online softmax update (row reductions across the 16 tx lanes)
        #pragma unroll
        for (int i = 0; i < 4; i++) {
            float rm = fmaxf(fmaxf(s[i][0], s[i][1]), fmaxf(s[i][2], s[i][3]));
            #pragma unroll
            for (int off = 8; off >= 1; off >>= 1)
                rm = fmaxf(rm, __shfl_xor_sync(0xffffffffu, rm, off));
            const float mnew = fmaxf(m_i[i], rm);
            const float corr = __expf(m_i[i] - mnew);
            m_i[i] = mnew;
            float rs = 0.f;
            #pragma unroll
            for (int j = 0; j < 4; j++) {
                s[i][j] = __expf(s[i][j] - mnew);
                rs += s[i][j];
            }
            #pragma unroll
            for (int off = 8; off >= 1; off >>= 1)
                rs += __shfl_xor_sync(0xffffffffu, rs, off);
            l_i[i] = l_i[i] * corr + rs;
            #pragma unroll
            for (int j = 0; j < 4; j++) o[i][j] *= corr;
        }

        __syncthreads();   // all score reads of KPs done
        // write P into KPs buffer
        #pragma unroll
        for (int i = 0; i < 4; i++)
            #pragma unroll
            for (int j = 0; j < 4; j++)
                KPs[(ty * 4 + i) * 65 + tx * 4 + j] = s[i][j];
        __syncthreads();

        // O += P @ V
        #pragma unroll 16
        for (int c = 0; c < 64; c++) {
            float p[4];
            #pragma unroll
            for (int i = 0; i < 4; i++) p[i] = KPs[(ty * 4 + i) * 65 + c];
            const float4 vv = *(const float4*)&Vs[c * 64 + tx * 4];
            #pragma unroll
            for (int i = 0; i < 4; i++) {
                o[i][0] = fmaf(p[i], vv.x, o[i][0]);
                o[i][1] = fmaf(p[i], vv.y, o[i][1]);
                o[i][2] = fmaf(p[i], vv.z, o[i][2]);
                o[i][3] = fmaf(p[i], vv.w, o[i][3]);
            }
        }
    }

    // epilogue: normalize, write concat[b, s, h*64+d]
    #pragma unroll
    for (int i = 0; i < 4; i++) {
        const float inv = 1.0f / l_i[i];
        const int row = q0 + ty * 4 + i;
        float4 r;
        r.x = o[i][0] * inv;
        r.y = o[i][1] * inv;
        r.z = o[i][2] * inv;
        r.w = o[i][3] * inv;
        float* dst = out_concat + ((size_t)(b * SS + row)) * DM + h * DK + tx * 4;
        *(float4*)dst = r;
    }
}

// ---------------------------------------------------------------------------
extern "C" void kernel_launch(void* const* d_in, const int* in_sizes, int n_in,
                              void* d_out, int out_size)
{
    const float* q    = (const float*)d_in[0];
    const float* k    = (const float*)d_in[1];
    const float* v    = (const float*)d_in[2];
    const int*   mask = (const int*)  d_in[3];
    const float* Wq   = (const float*)d_in[4];
    const float* bq   = (const float*)d_in[5];
    const float* Wk   = (const float*)d_in[6];
    const float* bk   = (const float*)d_in[7];
    const float* Wv   = (const float*)d_in[8];
    const float* bv   = (const float*)d_in[9];
    const float* Wo   = (const float*)d_in[10];
    const float* bo   = (const float*)d_in[11];
    float* out = (float*)d_out;

    float *qh, *kh, *vh, *ct;
    cudaGetSymbolAddress((void**)&qh, g_qh);
    cudaGetSymbolAddress((void**)&kh, g_kh);
    cudaGetSymbolAddress((void**)&vh, g_vh);
    cudaGetSymbolAddress((void**)&ct, g_ct);

    const dim3 gg(MROWS / 64, DM / 64);
    const dim3 bb(256);

    gemm_bias_kernel<true><<<gg, bb>>>(q, Wq, bq, qh);
    gemm_bias_kernel<true><<<gg, bb>>>(k, Wk, bk, kh);
    gemm_bias_kernel<true><<<gg, bb>>>(v, Wv, bv, vh);

    const size_t smem = (size_t)(2 * 64 * 65 + 64 * 64) * sizeof(float); // 49664
    cudaFuncSetAttribute(flash_kernel, cudaFuncAttributeMaxDynamicSharedMemorySize,
                         (int)smem);
    flash_kernel<<<dim3(SS / 64, BB * HH), 256, smem>>>(mask, ct);

    gemm_bias_kernel<false><<<gg, bb>>>(ct, Wo, bo, out);
}

// round 6
// speedup vs baseline: 1.9622x; 1.9622x over previous
#include <cuda_runtime.h>
#include <cstdint>

#define BB 4
#define SS 2048
#define DM 1024
#define HH 16
#define DK 64
#define MROWS (BB * SS)   // 8192

// scratch (allocation-free rule: __device__ globals)
__device__ float g_qh[BB * HH * SS * DK];
__device__ float g_kh[BB * HH * SS * DK];
__device__ float g_vh[BB * HH * SS * DK];
__device__ float g_ct[BB * SS * DM];

// ---------------------------------------------------------------------------
// helpers
// ---------------------------------------------------------------------------
__device__ __forceinline__ uint32_t f2tf32(float f) {
    uint32_t u;
    asm("cvt.rna.tf32.f32 %0, %1;" : "=r"(u) : "f"(f));
    return u;
}

__device__ __forceinline__ void ldsm_x4(uint32_t* r, uint32_t addr) {
    asm volatile("ldmatrix.sync.aligned.m8n8.x4.shared.b16 {%0,%1,%2,%3}, [%4];"
                 : "=r"(r[0]), "=r"(r[1]), "=r"(r[2]), "=r"(r[3]) : "r"(addr));
}

__device__ __forceinline__ void mma_tf32(float* c, const uint32_t* a,
                                         uint32_t b0, uint32_t b1) {
    asm volatile(
        "mma.sync.aligned.m16n8k8.row.col.f32.tf32.tf32.f32 "
        "{%0,%1,%2,%3},{%4,%5,%6,%7},{%8,%9},{%0,%1,%2,%3};"
        : "+f"(c[0]), "+f"(c[1]), "+f"(c[2]), "+f"(c[3])
        : "r"(a[0]), "r"(a[1]), "r"(a[2]), "r"(a[3]), "r"(b0), "r"(b1));
}

// ---------------------------------------------------------------------------
// tf32 GEMM:  Y[m,e] = sum_d X[m,d] * W[e,d] + bias[e]
// 128x128x16 CTA tile, 256 threads (8 warps, 2x4), m16n8k8 tf32 mma.
// ---------------------------------------------------------------------------
#define GP 20   // smem row pitch (floats): conflict-free for ldmatrix, 16B aligned

template <bool HEAD_OUT>
__global__ void __launch_bounds__(256) gemm_tf32(
    const float* __restrict__ X,     // [MROWS, DM]
    const float* __restrict__ W,     // [DM(e), DM(d)]
    const float* __restrict__ bias,  // [DM]
    float* __restrict__ Y)
{
    __shared__ uint32_t As[2][128 * GP];
    __shared__ uint32_t Bs[2][128 * GP];

    const int tid  = threadIdx.x;
    const int lane = tid & 31;
    const int warp = tid >> 5;
    const int wm   = warp >> 2;          // 0..1  (64 rows each)
    const int wn   = warp & 3;           // 0..3  (32 cols each)
    const int m0   = blockIdx.x * 128;
    const int e0   = blockIdx.y * 128;

    // loader mapping: 512 float4 per tile per matrix; each thread does 2
    const int lrow = tid >> 2;           // 0..63 (also +64)
    const int lkc  = (tid & 3) << 2;     // 0,4,8,12

    const float* Xp = X + (size_t)(m0 + lrow) * DM + lkc;
    const float* Wp = W + (size_t)(e0 + lrow) * DM + lkc;

    float4 ra0 = *(const float4*)(Xp);
    float4 ra1 = *(const float4*)(Xp + (size_t)64 * DM);
    float4 rb0 = *(const float4*)(Wp);
    float4 rb1 = *(const float4*)(Wp + (size_t)64 * DM);

    float c[4][4][4];
    #pragma unroll
    for (int i = 0; i < 4; i++)
        #pragma unroll
        for (int j = 0; j < 4; j++)
            #pragma unroll
            for (int r = 0; r < 4; r++) c[i][j][r] = 0.f;

    const uint32_t aBase = (uint32_t)__cvta_generic_to_shared(&As[0][0]);
    const uint32_t bBase = (uint32_t)__cvta_generic_to_shared(&Bs[0][0]);
    const uint32_t bufB  = 128 * GP * 4;

    // ldmatrix per-lane element offsets (b16 8x8 view == tf32 8-rows x 4-cols)
    const int aOff = (wm * 64 + (lane & 15)) * GP + (((lane & 16) >> 4) << 2);
    const int bOff = (wn * 32 + (lane & 7) + ((lane & 16) >> 1)) * GP + ((lane & 8) >> 1);

    int buf = 0;
    for (int kt = 0; kt < DM / 16; kt++) {
        // store staged tile (round-to-nearest tf32 conversion)
        uint32_t* a = &As[buf][0];
        uint32_t* bsm = &Bs[buf][0];
        int o0 = lrow * GP + lkc;
        int o1 = (lrow + 64) * GP + lkc;
        a[o0 + 0] = f2tf32(ra0.x); a[o0 + 1] = f2tf32(ra0.y);
        a[o0 + 2] = f2tf32(ra0.z); a[o0 + 3] = f2tf32(ra0.w);
        a[o1 + 0] = f2tf32(ra1.x); a[o1 + 1] = f2tf32(ra1.y);
        a[o1 + 2] = f2tf32(ra1.z); a[o1 + 3] = f2tf32(ra1.w);
        bsm[o0 + 0] = f2tf32(rb0.x); bsm[o0 + 1] = f2tf32(rb0.y);
        bsm[o0 + 2] = f2tf32(rb0.z); bsm[o0 + 3] = f2tf32(rb0.w);
        bsm[o1 + 0] = f2tf32(rb1.x); bsm[o1 + 1] = f2tf32(rb1.y);
        bsm[o1 + 2] = f2tf32(rb1.z); bsm[o1 + 3] = f2tf32(rb1.w);
        __syncthreads();

        if (kt + 1 < DM / 16) {
            const float* xp = Xp + (kt + 1) * 16;
            const float* wp = Wp + (kt + 1) * 16;
            ra0 = *(const float4*)(xp);
            ra1 = *(const float4*)(xp + (size_t)64 * DM);
            rb0 = *(const float4*)(wp);
            rb1 = *(const float4*)(wp + (size_t)64 * DM);
        }

        const uint32_t ab = aBase + buf * bufB;
        const uint32_t bb = bBase + buf * bufB;
        #pragma unroll
        for (int ks = 0; ks < 16; ks += 8) {
            uint32_t afr[4][4], bfr[2][4];
            #pragma unroll
            for (int mt = 0; mt < 4; mt++)
                ldsm_x4(afr[mt], ab + 4u * (aOff + mt * 16 * GP + ks));
            #pragma unroll
            for (int np = 0; np < 2; np++)
                ldsm_x4(bfr[np], bb + 4u * (bOff + np * 16 * GP + ks));
            #pragma unroll
            for (int mt = 0; mt < 4; mt++)
                #pragma unroll
                for (int nt = 0; nt < 4; nt++)
                    mma_tf32(c[mt][nt], afr[mt],
                             bfr[nt >> 1][(nt & 1) * 2],
                             bfr[nt >> 1][(nt & 1) * 2 + 1]);
        }
        buf ^= 1;
    }
    __syncthreads();

    // epilogue
    #pragma unroll
    for (int mt = 0; mt < 4; mt++) {
        #pragma unroll
        for (int nt = 0; nt < 4; nt++) {
            const int row = m0 + wm * 64 + mt * 16 + (lane >> 2);
            const int col = e0 + wn * 32 + nt * 8 + 2 * (lane & 3);
            const float2 bv = *(const float2*)(bias + col);
            float2 v0, v1;
            v0.x = c[mt][nt][0] + bv.x; v0.y = c[mt][nt][1] + bv.y;
            v1.x = c[mt][nt][2] + bv.x; v1.y = c[mt][nt][3] + bv.y;
            if (HEAD_OUT) {
                const int h = col >> 6, d = col & 63;
                const int b0_ = row >> 11, s0 = row & (SS - 1);
                float* d0 = Y + ((size_t)((b0_ * HH + h) * SS + s0)) * DK + d;
                float* d1 = Y + ((size_t)((b0_ * HH + h) * SS + s0 + 8)) * DK + d;
                *(float2*)d0 = v0;
                *(float2*)d1 = v1;
            } else {
                *(float2*)(Y + (size_t)row * DM + col) = v0;
                *(float2*)(Y + (size_t)(row + 8) * DM + col) = v1;
            }
        }
    }
}

// ---------------------------------------------------------------------------
// Flash attention fp32.
// CTA: 64 q-rows x 128 k-cols per iter, 128 threads (tx=0..15, ty=0..7).
// Score tile per thread: 8(q: ty*8+i) x 8(k: tx+16*j)  -> covers 64x128.
// PV output tile per thread: 8(q) x 4(dk: tx*4+j)       -> covers 64x64.
// smem: Qs[64][FP], KP[128][FP] (K tile, reused as P^T), Vs[128][FP].
// ---------------------------------------------------------------------------
#define FP 68

__global__ void __launch_bounds__(128) flash_kernel(
    const int* __restrict__ mask,    // [B,S,S]
    float* __restrict__ outc)        // [B,S,DM]
{
    extern __shared__ float sm[];
    float* Qs = sm;                        // [64][FP]
    float* KP = sm + 64 * FP;              // [128][FP]  K tile / P^T
    float* Vs = sm + 64 * FP + 128 * FP;   // [128][FP]

    const int tid = threadIdx.x;
    const int tx  = tid & 15;
    const int ty  = tid >> 4;              // 0..7
    const int bh  = blockIdx.y;
    const int b   = bh >> 4;
    const int h   = bh & 15;
    const int q0  = blockIdx.x * 64;

    const float* Qg = g_qh + ((size_t)bh * SS + q0) * DK;
    const float* Kg = g_kh + (size_t)bh * SS * DK;
    const float* Vg = g_vh + (size_t)bh * SS * DK;
    const int*   Mg = mask + (size_t)b * SS * SS + (size_t)q0 * SS;

    // load Q (scaled by 1/sqrt(dk))
    #pragma unroll
    for (int t = 0; t < 8; t++) {
        const int lin = t * 128 + tid;
        const int r = lin >> 4, c4 = (lin & 15) << 2;
        float4 q4 = *(const float4*)(Qg + r * DK + c4);
        q4.x *= 0.125f; q4.y *= 0.125f; q4.z *= 0.125f; q4.w *= 0.125f;
        *(float4*)&Qs[r * FP + c4] = q4;
    }

    float m_i[8], l_i[8], o[8][4];
    #pragma unroll
    for (int i = 0; i < 8; i++) {
        m_i[i] = -1e30f; l_i[i] = 0.f;
        #pragma unroll
        for (int j = 0; j < 4; j++) o[i][j] = 0.f;
    }

    for (int kt = 0; kt < SS / 128; kt++) {
        __syncthreads();   // prev PV reads of KP/Vs complete
        const float* kp = Kg + (size_t)kt * 128 * DK;
        const float* vp = Vg + (size_t)kt * 128 * DK;
        #pragma unroll
        for (int t = 0; t < 16; t++) {
            const int lin = t * 128 + tid;
            const int r = lin >> 4, c4 = (lin & 15) << 2;
            *(float4*)&KP[r * FP + c4] = *(const float4*)(kp + r * DK + c4);
            *(float4*)&Vs[r * FP + c4] = *(const float4*)(vp + r * DK + c4);
        }
        __syncthreads();

        // scores s[i][j] = Q[ty*8+i] . K[tx+16j]
        float s[8][8];
        #pragma unroll
        for (int i = 0; i < 8; i++)
            #pragma unroll
            for (int j = 0; j < 8; j++) s[i][j] = 0.f;

        #pragma unroll
        for (int kk = 0; kk < DK; kk += 4) {
            float4 b4[8];
            #pragma unroll
            for (int j = 0; j < 8; j++)
                b4[j] = *(const float4*)&KP[(tx + 16 * j) * FP + kk];
            #pragma unroll
            for (int i = 0; i < 8; i++) {
                const float4 a4 = *(const float4*)&Qs[(ty * 8 + i) * FP + kk];
                #pragma unroll
                for (int j = 0; j < 8; j++) {
                    s[i][j] = fmaf(a4.x, b4[j].x, s[i][j]);
                    s[i][j] = fmaf(a4.y, b4[j].y, s[i][j]);
                    s[i][j] = fmaf(a4.z, b4[j].z, s[i][j]);
                    s[i][j] = fmaf(a4.w, b4[j].w, s[i][j]);
                }
            }
        }

        // mask + online softmax (rows reduce across the 16 tx lanes)
        const int kbase = kt * 128 + tx;
        #pragma unroll
        for (int i = 0; i < 8; i++) {
            const int* mrow = Mg + (size_t)(ty * 8 + i) * SS + kbase;
            #pragma unroll
            for (int j = 0; j < 8; j++)
                if (mrow[16 * j] == 0) s[i][j] = -1e9f;

            float rm = s[i][0];
            #pragma unroll
            for (int j = 1; j < 8; j++) rm = fmaxf(rm, s[i][j]);
            #pragma unroll
            for (int off = 8; off >= 1; off >>= 1)
                rm = fmaxf(rm, __shfl_xor_sync(0xffffffffu, rm, off));
            const float mnew = fmaxf(m_i[i], rm);
            const float corr = __expf(m_i[i] - mnew);
            m_i[i] = mnew;
            float rs = 0.f;
            #pragma unroll
            for (int j = 0; j < 8; j++) {
                s[i][j] = __expf(s[i][j] - mnew);
                rs += s[i][j];
            }
            #pragma unroll
            for (int off = 8; off >= 1; off >>= 1)
                rs += __shfl_xor_sync(0xffffffffu, rs, off);
            l_i[i] = l_i[i] * corr + rs;
            #pragma unroll
            for (int j = 0; j < 4; j++) o[i][j] *= corr;
        }

        __syncthreads();   // all score reads of K done
        // write P^T over KP: PsT[kcol][qrow]
        #pragma unroll
        for (int j = 0; j < 8; j++) {
            float* dst = &KP[(tx + 16 * j) * FP + ty * 8];
            *(float4*)(dst)     = make_float4(s[0][j], s[1][j], s[2][j], s[3][j]);
            *(float4*)(dst + 4) = make_float4(s[4][j], s[5][j], s[6][j], s[7][j]);
        }
        __syncthreads();

        // O += P @ V   (contraction over the 128 k positions)
        #pragma unroll 8
        for (int cc = 0; cc < 128; cc++) {
            const float4 p_lo = *(const float4*)&KP[cc * FP + ty * 8];
            const float4 p_hi = *(const float4*)&KP[cc * FP + ty * 8 + 4];
            const float4 vv   = *(const float4*)&Vs[cc * FP + tx * 4];
            const float p[8] = {p_lo.x, p_lo.y, p_lo.z, p_lo.w,
                                p_hi.x, p_hi.y, p_hi.z, p_hi.w};
            #pragma unroll
            for (int i = 0; i < 8; i++) {
                o[i][0] = fmaf(p[i], vv.x, o[i][0]);
                o[i][1] = fmaf(p[i], vv.y, o[i][1]);
                o[i][2] = fmaf(p[i], vv.z, o[i][2]);
                o[i][3] = fmaf(p[i], vv.w, o[i][3]);
            }
        }
    }

    // epilogue: normalize, write concat[b, s, h*64 + d]
    #pragma unroll
    for (int i = 0; i < 8; i++) {
        const float inv = 1.0f / l_i[i];
        const int row = q0 + ty * 8 + i;
        float* dst = outc + ((size_t)(b * SS + row)) * DM + h * DK + tx * 4;
        float4 r0 = make_float4(o[i][0] * inv, o[i][1] * inv,
                                o[i][2] * inv, o[i][3] * inv);
        *(float4*)dst = r0;
    }
}

// ---------------------------------------------------------------------------
extern "C" void kernel_launch(void* const* d_in, const int* in_sizes, int n_in,
                              void* d_out, int out_size)
{
    const float* q    = (const float*)d_in[0];
    const float* k    = (const float*)d_in[1];
    const float* v    = (const float*)d_in[2];
    const int*   mask = (const int*)  d_in[3];
    const float* Wq   = (const float*)d_in[4];
    const float* bq   = (const float*)d_in[5];
    const float* Wk   = (const float*)d_in[6];
    const float* bk   = (const float*)d_in[7];
    const float* Wv   = (const float*)d_in[8];
    const float* bv   = (const float*)d_in[9];
    const float* Wo   = (const float*)d_in[10];
    const float* bo   = (const float*)d_in[11];
    float* out = (float*)d_out;

    float *qh, *kh, *vh, *ct;
    cudaGetSymbolAddress((void**)&qh, g_qh);
    cudaGetSymbolAddress((void**)&kh, g_kh);
    cudaGetSymbolAddress((void**)&vh, g_vh);
    cudaGetSymbolAddress((void**)&ct, g_ct);

    const dim3 gg(MROWS / 128, DM / 128);
    const dim3 bb(256);

    gemm_tf32<true><<<gg, bb>>>(q, Wq, bq, qh);
    gemm_tf32<true><<<gg, bb>>>(k, Wk, bk, kh);
    gemm_tf32<true><<<gg, bb>>>(v, Wv, bv, vh);

    const size_t smem = (size_t)(64 + 128 + 128) * FP * sizeof(float); // 87040
    cudaFuncSetAttribute(flash_kernel, cudaFuncAttributeMaxDynamicSharedMemorySize,
                         (int)smem);
    flash_kernel<<<dim3(SS / 64, BB * HH), 128, smem>>>(mask, ct);

    gemm_tf32<false><<<gg, bb>>>(ct, Wo, bo, out);
}

// round 7
// speedup vs baseline: 3.3434x; 1.7039x over previous
#include <cuda_runtime.h>
#include <cstdint>

#define BB 4
#define SS 2048
#define DM 1024
#define HH 16
#define DK 64
#define MROWS (BB * SS)   // 8192

// scratch (allocation-free rule: __device__ globals)
__device__ float g_qh[BB * HH * SS * DK];
__device__ float g_kh[BB * HH * SS * DK];
__device__ float g_vh[BB * HH * SS * DK];
__device__ float g_ct[BB * SS * DM];

// ---------------------------------------------------------------------------
// helpers
// ---------------------------------------------------------------------------
__device__ __forceinline__ uint32_t f2tf32(float f) {
    uint32_t u;
    asm("cvt.rna.tf32.f32 %0, %1;" : "=r"(u) : "f"(f));
    return u;
}

__device__ __forceinline__ void ldsm_x4(uint32_t* r, uint32_t addr) {
    asm volatile("ldmatrix.sync.aligned.m8n8.x4.shared.b16 {%0,%1,%2,%3}, [%4];"
                 : "=r"(r[0]), "=r"(r[1]), "=r"(r[2]), "=r"(r[3]) : "r"(addr));
}

__device__ __forceinline__ void mma_tf32(float* c, const uint32_t* a,
                                         uint32_t b0, uint32_t b1) {
    asm volatile(
        "mma.sync.aligned.m16n8k8.row.col.f32.tf32.tf32.f32 "
        "{%0,%1,%2,%3},{%4,%5,%6,%7},{%8,%9},{%0,%1,%2,%3};"
        : "+f"(c[0]), "+f"(c[1]), "+f"(c[2]), "+f"(c[3])
        : "r"(a[0]), "r"(a[1]), "r"(a[2]), "r"(a[3]), "r"(b0), "r"(b1));
}

// ---------------------------------------------------------------------------
// tf32 GEMM:  Y[m,e] = sum_d X[m,d] * W[e,d] + bias[e]
// 128x128x16 CTA tile, 256 threads (8 warps, 2x4), m16n8k8 tf32 mma.
// (unchanged from round 6 — validated)
// ---------------------------------------------------------------------------
#define GP 20

template <bool HEAD_OUT>
__global__ void __launch_bounds__(256) gemm_tf32(
    const float* __restrict__ X,
    const float* __restrict__ W,
    const float* __restrict__ bias,
    float* __restrict__ Y)
{
    __shared__ uint32_t As[2][128 * GP];
    __shared__ uint32_t Bs[2][128 * GP];

    const int tid  = threadIdx.x;
    const int lane = tid & 31;
    const int warp = tid >> 5;
    const int wm   = warp >> 2;
    const int wn   = warp & 3;
    const int m0   = blockIdx.x * 128;
    const int e0   = blockIdx.y * 128;

    const int lrow = tid >> 2;
    const int lkc  = (tid & 3) << 2;

    const float* Xp = X + (size_t)(m0 + lrow) * DM + lkc;
    const float* Wp = W + (size_t)(e0 + lrow) * DM + lkc;

    float4 ra0 = *(const float4*)(Xp);
    float4 ra1 = *(const float4*)(Xp + (size_t)64 * DM);
    float4 rb0 = *(const float4*)(Wp);
    float4 rb1 = *(const float4*)(Wp + (size_t)64 * DM);

    float c[4][4][4];
    #pragma unroll
    for (int i = 0; i < 4; i++)
        #pragma unroll
        for (int j = 0; j < 4; j++)
            #pragma unroll
            for (int r = 0; r < 4; r++) c[i][j][r] = 0.f;

    const uint32_t aBase = (uint32_t)__cvta_generic_to_shared(&As[0][0]);
    const uint32_t bBase = (uint32_t)__cvta_generic_to_shared(&Bs[0][0]);
    const uint32_t bufB  = 128 * GP * 4;

    const int aOff = (wm * 64 + (lane & 15)) * GP + (((lane & 16) >> 4) << 2);
    const int bOff = (wn * 32 + (lane & 7) + ((lane & 16) >> 1)) * GP + ((lane & 8) >> 1);

    int buf = 0;
    for (int kt = 0; kt < DM / 16; kt++) {
        uint32_t* a = &As[buf][0];
        uint32_t* bsm = &Bs[buf][0];
        int o0 = lrow * GP + lkc;
        int o1 = (lrow + 64) * GP + lkc;
        a[o0 + 0] = f2tf32(ra0.x); a[o0 + 1] = f2tf32(ra0.y);
        a[o0 + 2] = f2tf32(ra0.z); a[o0 + 3] = f2tf32(ra0.w);
        a[o1 + 0] = f2tf32(ra1.x); a[o1 + 1] = f2tf32(ra1.y);
        a[o1 + 2] = f2tf32(ra1.z); a[o1 + 3] = f2tf32(ra1.w);
        bsm[o0 + 0] = f2tf32(rb0.x); bsm[o0 + 1] = f2tf32(rb0.y);
        bsm[o0 + 2] = f2tf32(rb0.z); bsm[o0 + 3] = f2tf32(rb0.w);
        bsm[o1 + 0] = f2tf32(rb1.x); bsm[o1 + 1] = f2tf32(rb1.y);
        bsm[o1 + 2] = f2tf32(rb1.z); bsm[o1 + 3] = f2tf32(rb1.w);
        __syncthreads();

        if (kt + 1 < DM / 16) {
            const float* xp = Xp + (kt + 1) * 16;
            const float* wp = Wp + (kt + 1) * 16;
            ra0 = *(const float4*)(xp);
            ra1 = *(const float4*)(xp + (size_t)64 * DM);
            rb0 = *(const float4*)(wp);
            rb1 = *(const float4*)(wp + (size_t)64 * DM);
        }

        const uint32_t ab = aBase + buf * bufB;
        const uint32_t bb = bBase + buf * bufB;
        #pragma unroll
        for (int ks = 0; ks < 16; ks += 8) {
            uint32_t afr[4][4], bfr[2][4];
            #pragma unroll
            for (int mt = 0; mt < 4; mt++)
                ldsm_x4(afr[mt], ab + 4u * (aOff + mt * 16 * GP + ks));
            #pragma unroll
            for (int np = 0; np < 2; np++)
                ldsm_x4(bfr[np], bb + 4u * (bOff + np * 16 * GP + ks));
            #pragma unroll
            for (int mt = 0; mt < 4; mt++)
                #pragma unroll
                for (int nt = 0; nt < 4; nt++)
                    mma_tf32(c[mt][nt], afr[mt],
                             bfr[nt >> 1][(nt & 1) * 2],
                             bfr[nt >> 1][(nt & 1) * 2 + 1]);
        }
        buf ^= 1;
    }
    __syncthreads();

    #pragma unroll
    for (int mt = 0; mt < 4; mt++) {
        #pragma unroll
        for (int nt = 0; nt < 4; nt++) {
            const int row = m0 + wm * 64 + mt * 16 + (lane >> 2);
            const int col = e0 + wn * 32 + nt * 8 + 2 * (lane & 3);
            const float2 bv = *(const float2*)(bias + col);
            float2 v0, v1;
            v0.x = c[mt][nt][0] + bv.x; v0.y = c[mt][nt][1] + bv.y;
            v1.x = c[mt][nt][2] + bv.x; v1.y = c[mt][nt][3] + bv.y;
            if (HEAD_OUT) {
                const int h = col >> 6, d = col & 63;
                const int b0_ = row >> 11, s0 = row & (SS - 1);
                float* d0 = Y + ((size_t)((b0_ * HH + h) * SS + s0)) * DK + d;
                float* d1 = Y + ((size_t)((b0_ * HH + h) * SS + s0 + 8)) * DK + d;
                *(float2*)d0 = v0;
                *(float2*)d1 = v1;
            } else {
                *(float2*)(Y + (size_t)row * DM + col) = v0;
                *(float2*)(Y + (size_t)(row + 8) * DM + col) = v1;
            }
        }
    }
}

// ---------------------------------------------------------------------------
// Tensor-core flash attention (tf32 mma, fp32 softmax).
// CTA: 64 q-rows, KV tiles of 128. 128 threads = 4 warps; warp w owns q-rows
// [w*16, w*16+16).
// smem: Qs[64][68] tf32, Ks[128][68] tf32 (reused as Ps[64][132] tf32),
//       Vt[64][132] tf32 (V transposed: [dk][kpos]).
// ---------------------------------------------------------------------------
#define QP  68
#define KSP 68
#define VTP 132
#define PSP 132

__global__ void __launch_bounds__(128) flash_mma(
    const int* __restrict__ mask,    // [B,S,S]
    float* __restrict__ outc)        // [B,S,DM]
{
    extern __shared__ float sm[];
    float* Qs = sm;                       // 64*QP
    float* Ks = sm + 64 * QP;             // 128*KSP (aliased by Ps: 64*PSP=8448<=8704)
    float* Vt = sm + 64 * QP + 128 * KSP; // 64*VTP

    const int tid  = threadIdx.x;
    const int lane = tid & 31;
    const int w    = tid >> 5;           // 0..3
    const int g    = lane >> 2;          // 0..7 (row in octet)
    const int tig  = lane & 3;           // 0..3

    const int bh = blockIdx.y;
    const int b  = bh >> 4;
    const int h  = bh & 15;
    const int q0 = blockIdx.x * 64;

    const float* Qg = g_qh + ((size_t)bh * SS + q0) * DK;
    const float* Kg = g_kh + (size_t)bh * SS * DK;
    const float* Vg = g_vh + (size_t)bh * SS * DK;
    const int*   Mg = mask + (size_t)b * SS * SS + (size_t)q0 * SS;

    uint32_t* Qu = (uint32_t*)Qs;
    uint32_t* Ku = (uint32_t*)Ks;
    uint32_t* Pu = (uint32_t*)Ks;   // alias
    uint32_t* Vu = (uint32_t*)Vt;

    // load Q (scaled by 1/8, tf32-converted)
    #pragma unroll
    for (int t = 0; t < 8; t++) {
        const int lin = t * 128 + tid;
        const int r = lin >> 4, c4 = (lin & 15) << 2;
        float4 q4 = *(const float4*)(Qg + r * DK + c4);
        Qu[r * QP + c4 + 0] = f2tf32(q4.x * 0.125f);
        Qu[r * QP + c4 + 1] = f2tf32(q4.y * 0.125f);
        Qu[r * QP + c4 + 2] = f2tf32(q4.z * 0.125f);
        Qu[r * QP + c4 + 3] = f2tf32(q4.w * 0.125f);
    }

    const uint32_t qBase = (uint32_t)__cvta_generic_to_shared(Qs);
    const uint32_t kBase = (uint32_t)__cvta_generic_to_shared(Ks);
    const uint32_t vBase = (uint32_t)__cvta_generic_to_shared(Vt);

    // fragment lane offsets (element units)
    const int aOffQ = (w * 16 + (lane & 15)) * QP + (((lane & 16) >> 4) << 2);
    const int aOffP = (w * 16 + (lane & 15)) * PSP + (((lane & 16) >> 4) << 2);
    const int bRow  = (lane & 7) + ((lane & 16) >> 1);   // 0..15
    const int bK    = (lane & 8) >> 1;                   // 0 or 4

    float m0v = -1e30f, m1v = -1e30f, l0v = 0.f, l1v = 0.f;
    float of[8][4];
    #pragma unroll
    for (int j = 0; j < 8; j++)
        #pragma unroll
        for (int r = 0; r < 4; r++) of[j][r] = 0.f;

    for (int kt = 0; kt < SS / 128; kt++) {
        __syncthreads();   // previous-iter smem consumers done

        // --- load K tile [128 kpos][64 dk] ---
        const float* kp = Kg + (size_t)kt * 128 * DK;
        #pragma unroll
        for (int t = 0; t < 16; t++) {
            const int lin = t * 128 + tid;
            const int r = lin >> 4, c4 = (lin & 15) << 2;
            float4 kv = *(const float4*)(kp + r * DK + c4);
            Ku[r * KSP + c4 + 0] = f2tf32(kv.x);
            Ku[r * KSP + c4 + 1] = f2tf32(kv.y);
            Ku[r * KSP + c4 + 2] = f2tf32(kv.z);
            Ku[r * KSP + c4 + 3] = f2tf32(kv.w);
        }
        // --- load V transposed: Vt[d][kpos] ---
        const float* vp = Vg + (size_t)kt * 128 * DK;
        #pragma unroll
        for (int t = 0; t < 16; t++) {
            const int lin = t * 128 + tid;
            const int d = lin & 63;
            const int kp4 = (lin >> 6) << 2;
            uint4 pv;
            pv.x = f2tf32(vp[(size_t)(kp4 + 0) * DK + d]);
            pv.y = f2tf32(vp[(size_t)(kp4 + 1) * DK + d]);
            pv.z = f2tf32(vp[(size_t)(kp4 + 2) * DK + d]);
            pv.w = f2tf32(vp[(size_t)(kp4 + 3) * DK + d]);
            *(uint4*)&Vu[d * VTP + kp4] = pv;
        }
        __syncthreads();

        // --- S = Q K^T : warp computes 16 x 128 ---
        uint32_t af[8][4];
        #pragma unroll
        for (int ks = 0; ks < 8; ks++)
            ldsm_x4(af[ks], qBase + 4u * (aOffQ + ks * 8));

        float sfr[16][4];
        #pragma unroll
        for (int nt = 0; nt < 16; nt++)
            #pragma unroll
            for (int r = 0; r < 4; r++) sfr[nt][r] = 0.f;

        #pragma unroll
        for (int ks = 0; ks < 8; ks++) {
            #pragma unroll
            for (int np = 0; np < 8; np++) {
                uint32_t bf[4];
                ldsm_x4(bf, kBase + 4u * ((bRow + np * 16) * KSP + bK + ks * 8));
                mma_tf32(sfr[2 * np],     af[ks], bf[0], bf[1]);
                mma_tf32(sfr[2 * np + 1], af[ks], bf[2], bf[3]);
            }
        }

        // --- mask + online softmax on fragments ---
        const int* mrow0 = Mg + (size_t)(w * 16 + g) * SS + kt * 128;
        const int* mrow1 = mrow0 + 8 * SS;
        #pragma unroll
        for (int nt = 0; nt < 16; nt++) {
            const int2 mm0 = *(const int2*)(mrow0 + nt * 8 + 2 * tig);
            const int2 mm1 = *(const int2*)(mrow1 + nt * 8 + 2 * tig);
            if (mm0.x == 0) sfr[nt][0] = -1e9f;
            if (mm0.y == 0) sfr[nt][1] = -1e9f;
            if (mm1.x == 0) sfr[nt][2] = -1e9f;
            if (mm1.y == 0) sfr[nt][3] = -1e9f;
        }

        float pm0 = -1e30f, pm1 = -1e30f;
        #pragma unroll
        for (int nt = 0; nt < 16; nt++) {
            pm0 = fmaxf(pm0, fmaxf(sfr[nt][0], sfr[nt][1]));
            pm1 = fmaxf(pm1, fmaxf(sfr[nt][2], sfr[nt][3]));
        }
        pm0 = fmaxf(pm0, __shfl_xor_sync(0xffffffffu, pm0, 1));
        pm0 = fmaxf(pm0, __shfl_xor_sync(0xffffffffu, pm0, 2));
        pm1 = fmaxf(pm1, __shfl_xor_sync(0xffffffffu, pm1, 1));
        pm1 = fmaxf(pm1, __shfl_xor_sync(0xffffffffu, pm1, 2));

        const float mn0 = fmaxf(m0v, pm0);
        const float mn1 = fmaxf(m1v, pm1);
        const float cr0 = __expf(m0v - mn0);
        const float cr1 = __expf(m1v - mn1);
        m0v = mn0; m1v = mn1;

        float rs0 = 0.f, rs1 = 0.f;
        #pragma unroll
        for (int nt = 0; nt < 16; nt++) {
            sfr[nt][0] = __expf(sfr[nt][0] - mn0);
            sfr[nt][1] = __expf(sfr[nt][1] - mn0);
            sfr[nt][2] = __expf(sfr[nt][2] - mn1);
            sfr[nt][3] = __expf(sfr[nt][3] - mn1);
            rs0 += sfr[nt][0] + sfr[nt][1];
            rs1 += sfr[nt][2] + sfr[nt][3];
        }
        rs0 += __shfl_xor_sync(0xffffffffu, rs0, 1);
        rs0 += __shfl_xor_sync(0xffffffffu, rs0, 2);
        rs1 += __shfl_xor_sync(0xffffffffu, rs1, 1);
        rs1 += __shfl_xor_sync(0xffffffffu, rs1, 2);
        l0v = l0v * cr0 + rs0;
        l1v = l1v * cr1 + rs1;

        #pragma unroll
        for (int j = 0; j < 8; j++) {
            of[j][0] *= cr0; of[j][1] *= cr0;
            of[j][2] *= cr1; of[j][3] *= cr1;
        }

        __syncthreads();   // all S-phase reads of Ks done

        // --- store P (tf32) into Ps[64][PSP] (aliases Ks) ---
        const int pr0 = w * 16 + g;
        #pragma unroll
        for (int nt = 0; nt < 16; nt++) {
            uint2 p0, p1;
            p0.x = f2tf32(sfr[nt][0]); p0.y = f2tf32(sfr[nt][1]);
            p1.x = f2tf32(sfr[nt][2]); p1.y = f2tf32(sfr[nt][3]);
            *(uint2*)&Pu[pr0 * PSP + nt * 8 + 2 * tig] = p0;
            *(uint2*)&Pu[(pr0 + 8) * PSP + nt * 8 + 2 * tig] = p1;
        }
        __syncthreads();

        // --- O += P V : warp computes 16 x 64, contraction over 128 ---
        #pragma unroll
        for (int ks = 0; ks < 16; ks++) {
            uint32_t ap[4];
            ldsm_x4(ap, kBase + 4u * (aOffP + ks * 8));
            #pragma unroll
            for (int np = 0; np < 4; np++) {
                uint32_t bf[4];
                ldsm_x4(bf, vBase + 4u * ((bRow + np * 16) * VTP + bK + ks * 8));
                mma_tf32(of[2 * np],     ap, bf[0], bf[1]);
                mma_tf32(of[2 * np + 1], ap, bf[2], bf[3]);
            }
        }
    }

    // epilogue: normalize, write concat[b, s, h*64 + d]
    const float inv0 = 1.0f / l0v;
    const float inv1 = 1.0f / l1v;
    const int row0 = q0 + w * 16 + g;
    #pragma unroll
    for (int nt = 0; nt < 8; nt++) {
        const int col = h * DK + nt * 8 + 2 * tig;
        float2 r0, r1;
        r0.x = of[nt][0] * inv0; r0.y = of[nt][1] * inv0;
        r1.x = of[nt][2] * inv1; r1.y = of[nt][3] * inv1;
        *(float2*)&outc[((size_t)(b * SS + row0)) * DM + col] = r0;
        *(float2*)&outc[((size_t)(b * SS + row0 + 8)) * DM + col] = r1;
    }
}

// ---------------------------------------------------------------------------
extern "C" void kernel_launch(void* const* d_in, const int* in_sizes, int n_in,
                              void* d_out, int out_size)
{
    const float* q    = (const float*)d_in[0];
    const float* k    = (const float*)d_in[1];
    const float* v    = (const float*)d_in[2];
    const int*   mask = (const int*)  d_in[3];
    const float* Wq   = (const float*)d_in[4];
    const float* bq   = (const float*)d_in[5];
    const float* Wk   = (const float*)d_in[6];
    const float* bk   = (const float*)d_in[7];
    const float* Wv   = (const float*)d_in[8];
    const float* bv   = (const float*)d_in[9];
    const float* Wo   = (const float*)d_in[10];
    const float* bo   = (const float*)d_in[11];
    float* out = (float*)d_out;

    float *qh, *kh, *vh, *ct;
    cudaGetSymbolAddress((void**)&qh, g_qh);
    cudaGetSymbolAddress((void**)&kh, g_kh);
    cudaGetSymbolAddress((void**)&vh, g_vh);
    cudaGetSymbolAddress((void**)&ct, g_ct);

    const dim3 gg(MROWS / 128, DM / 128);
    const dim3 bb(256);

    gemm_tf32<true><<<gg, bb>>>(q, Wq, bq, qh);
    gemm_tf32<true><<<gg, bb>>>(k, Wk, bk, kh);
    gemm_tf32<true><<<gg, bb>>>(v, Wv, bv, vh);

    const size_t smem = (size_t)(64 * QP + 128 * KSP + 64 * VTP) * sizeof(float); // 86016
    cudaFuncSetAttribute(flash_mma, cudaFuncAttributeMaxDynamicSharedMemorySize,
                         (int)smem);
    flash_mma<<<dim3(SS / 64, BB * HH), 128, smem>>>(mask, ct);

    gemm_tf32<false><<<gg, bb>>>(ct, Wo, bo, out);
}

// round 8
// speedup vs baseline: 4.1618x; 1.2448x over previous
#include <cuda_runtime.h>
#include <cuda_fp16.h>
#include <cstdint>

#define BB 4
#define SS 2048
#define DM 1024
#define HH 16
#define DK 64
#define MROWS (BB * SS)   // 8192

// scratch (allocation-free rule: __device__ globals)
__device__ float g_qh[BB * HH * SS * DK];
__device__ float g_kh[BB * HH * SS * DK];
__device__ float g_vh[BB * HH * SS * DK];
__device__ float g_ct[BB * SS * DM];

// ---------------------------------------------------------------------------
// helpers
// ---------------------------------------------------------------------------
__device__ __forceinline__ uint32_t f2tf32(float f) {
    uint32_t u;
    asm("cvt.rna.tf32.f32 %0, %1;" : "=r"(u) : "f"(f));
    return u;
}

__device__ __forceinline__ void ldsm_x4(uint32_t* r, uint32_t addr) {
    asm volatile("ldmatrix.sync.aligned.m8n8.x4.shared.b16 {%0,%1,%2,%3}, [%4];"
                 : "=r"(r[0]), "=r"(r[1]), "=r"(r[2]), "=r"(r[3]) : "r"(addr));
}

__device__ __forceinline__ void mma_tf32(float* c, const uint32_t* a,
                                         uint32_t b0, uint32_t b1) {
    asm volatile(
        "mma.sync.aligned.m16n8k8.row.col.f32.tf32.tf32.f32 "
        "{%0,%1,%2,%3},{%4,%5,%6,%7},{%8,%9},{%0,%1,%2,%3};"
        : "+f"(c[0]), "+f"(c[1]), "+f"(c[2]), "+f"(c[3])
        : "r"(a[0]), "r"(a[1]), "r"(a[2]), "r"(a[3]), "r"(b0), "r"(b1));
}

__device__ __forceinline__ void mma_f16(float* c, const uint32_t* a,
                                        uint32_t b0, uint32_t b1) {
    asm volatile(
        "mma.sync.aligned.m16n8k16.row.col.f32.f16.f16.f32 "
        "{%0,%1,%2,%3},{%4,%5,%6,%7},{%8,%9},{%0,%1,%2,%3};"
        : "+f"(c[0]), "+f"(c[1]), "+f"(c[2]), "+f"(c[3])
        : "r"(a[0]), "r"(a[1]), "r"(a[2]), "r"(a[3]), "r"(b0), "r"(b1));
}

__device__ __forceinline__ uint32_t pack_h2(float lo, float hi) {
    __half2 h = __floats2half2_rn(lo, hi);
    return *(uint32_t*)&h;
}

// ---------------------------------------------------------------------------
// tf32 GEMM (unchanged — validated in rounds 6/7)
// ---------------------------------------------------------------------------
#define GP 20

template <bool HEAD_OUT>
__global__ void __launch_bounds__(256) gemm_tf32(
    const float* __restrict__ X,
    const float* __restrict__ W,
    const float* __restrict__ bias,
    float* __restrict__ Y)
{
    __shared__ uint32_t As[2][128 * GP];
    __shared__ uint32_t Bs[2][128 * GP];

    const int tid  = threadIdx.x;
    const int lane = tid & 31;
    const int warp = tid >> 5;
    const int wm   = warp >> 2;
    const int wn   = warp & 3;
    const int m0   = blockIdx.x * 128;
    const int e0   = blockIdx.y * 128;

    const int lrow = tid >> 2;
    const int lkc  = (tid & 3) << 2;

    const float* Xp = X + (size_t)(m0 + lrow) * DM + lkc;
    const float* Wp = W + (size_t)(e0 + lrow) * DM + lkc;

    float4 ra0 = *(const float4*)(Xp);
    float4 ra1 = *(const float4*)(Xp + (size_t)64 * DM);
    float4 rb0 = *(const float4*)(Wp);
    float4 rb1 = *(const float4*)(Wp + (size_t)64 * DM);

    float c[4][4][4];
    #pragma unroll
    for (int i = 0; i < 4; i++)
        #pragma unroll
        for (int j = 0; j < 4; j++)
            #pragma unroll
            for (int r = 0; r < 4; r++) c[i][j][r] = 0.f;

    const uint32_t aBase = (uint32_t)__cvta_generic_to_shared(&As[0][0]);
    const uint32_t bBase = (uint32_t)__cvta_generic_to_shared(&Bs[0][0]);
    const uint32_t bufB  = 128 * GP * 4;

    const int aOff = (wm * 64 + (lane & 15)) * GP + (((lane & 16) >> 4) << 2);
    const int bOff = (wn * 32 + (lane & 7) + ((lane & 16) >> 1)) * GP + ((lane & 8) >> 1);

    int buf = 0;
    for (int kt = 0; kt < DM / 16; kt++) {
        uint32_t* a = &As[buf][0];
        uint32_t* bsm = &Bs[buf][0];
        int o0 = lrow * GP + lkc;
        int o1 = (lrow + 64) * GP + lkc;
        a[o0 + 0] = f2tf32(ra0.x); a[o0 + 1] = f2tf32(ra0.y);
        a[o0 + 2] = f2tf32(ra0.z); a[o0 + 3] = f2tf32(ra0.w);
        a[o1 + 0] = f2tf32(ra1.x); a[o1 + 1] = f2tf32(ra1.y);
        a[o1 + 2] = f2tf32(ra1.z); a[o1 + 3] = f2tf32(ra1.w);
        bsm[o0 + 0] = f2tf32(rb0.x); bsm[o0 + 1] = f2tf32(rb0.y);
        bsm[o0 + 2] = f2tf32(rb0.z); bsm[o0 + 3] = f2tf32(rb0.w);
        bsm[o1 + 0] = f2tf32(rb1.x); bsm[o1 + 1] = f2tf32(rb1.y);
        bsm[o1 + 2] = f2tf32(rb1.z); bsm[o1 + 3] = f2tf32(rb1.w);
        __syncthreads();

        if (kt + 1 < DM / 16) {
            const float* xp = Xp + (kt + 1) * 16;
            const float* wp = Wp + (kt + 1) * 16;
            ra0 = *(const float4*)(xp);
            ra1 = *(const float4*)(xp + (size_t)64 * DM);
            rb0 = *(const float4*)(wp);
            rb1 = *(const float4*)(wp + (size_t)64 * DM);
        }

        const uint32_t ab = aBase + buf * bufB;
        const uint32_t bb = bBase + buf * bufB;
        #pragma unroll
        for (int ks = 0; ks < 16; ks += 8) {
            uint32_t afr[4][4], bfr[2][4];
            #pragma unroll
            for (int mt = 0; mt < 4; mt++)
                ldsm_x4(afr[mt], ab + 4u * (aOff + mt * 16 * GP + ks));
            #pragma unroll
            for (int np = 0; np < 2; np++)
                ldsm_x4(bfr[np], bb + 4u * (bOff + np * 16 * GP + ks));
            #pragma unroll
            for (int mt = 0; mt < 4; mt++)
                #pragma unroll
                for (int nt = 0; nt < 4; nt++)
                    mma_tf32(c[mt][nt], afr[mt],
                             bfr[nt >> 1][(nt & 1) * 2],
                             bfr[nt >> 1][(nt & 1) * 2 + 1]);
        }
        buf ^= 1;
    }
    __syncthreads();

    #pragma unroll
    for (int mt = 0; mt < 4; mt++) {
        #pragma unroll
        for (int nt = 0; nt < 4; nt++) {
            const int row = m0 + wm * 64 + mt * 16 + (lane >> 2);
            const int col = e0 + wn * 32 + nt * 8 + 2 * (lane & 3);
            const float2 bv = *(const float2*)(bias + col);
            float2 v0, v1;
            v0.x = c[mt][nt][0] + bv.x; v0.y = c[mt][nt][1] + bv.y;
            v1.x = c[mt][nt][2] + bv.x; v1.y = c[mt][nt][3] + bv.y;
            if (HEAD_OUT) {
                const int h = col >> 6, d = col & 63;
                const int b0_ = row >> 11, s0 = row & (SS - 1);
                float* d0 = Y + ((size_t)((b0_ * HH + h) * SS + s0)) * DK + d;
                float* d1 = Y + ((size_t)((b0_ * HH + h) * SS + s0 + 8)) * DK + d;
                *(float2*)d0 = v0;
                *(float2*)d1 = v1;
            } else {
                *(float2*)(Y + (size_t)row * DM + col) = v0;
                *(float2*)(Y + (size_t)(row + 8) * DM + col) = v1;
            }
        }
    }
}

// ---------------------------------------------------------------------------
// fp16 flash attention (FA2-style): m16n8k16 mma, fp32 softmax/accum.
// CTA: 64 q-rows, KV tiles of 128, 128 threads = 4 warps (16 q-rows each).
// Q fragments preloaded to registers; P never touches smem (C->A reuse).
// smem (fp16): Kh[128][KP], Vt[64][VP] (V transposed); Q staged over Kh.
// ---------------------------------------------------------------------------
#define KP  72    // halves; 144B row stride -> conflict-free ldsm
#define VP  136   // halves; 272B row stride -> conflict-free ldsm
#define FLASH_SMEM (128 * KP * 2 + 64 * VP * 2)   // 18432 + 17408 = 35840 B

__global__ void __launch_bounds__(128, 3) flash_f16(
    const int* __restrict__ mask,    // [B,S,S]
    float* __restrict__ outc)        // [B,S,DM]
{
    extern __shared__ __half smh[];
    __half* Kh = smh;                 // [128][KP]
    __half* Vt = smh + 128 * KP;      // [64][VP]
    __half* Qh = smh;                 // staging, aliased over Kh

    const int tid  = threadIdx.x;
    const int lane = tid & 31;
    const int w    = tid >> 5;        // 0..3
    const int g    = lane >> 2;       // 0..7
    const int tig  = lane & 3;        // 0..3

    const int bh = blockIdx.y;
    const int b  = bh >> 4;
    const int h  = bh & 15;
    const int q0 = blockIdx.x * 64;

    const float* Qg = g_qh + ((size_t)bh * SS + q0) * DK;
    const float* Kg = g_kh + (size_t)bh * SS * DK;
    const float* Vg = g_vh + (size_t)bh * SS * DK;
    const int*   Mg = mask + (size_t)b * SS * SS + (size_t)q0 * SS;

    const uint32_t kBase = (uint32_t)__cvta_generic_to_shared(Kh);
    const uint32_t vBase = (uint32_t)__cvta_generic_to_shared(Vt);
    const uint32_t qBase = (uint32_t)__cvta_generic_to_shared(Qh);

    // ---- stage Q (scaled), ldsm Q fragments into registers ----
    #pragma unroll
    for (int t = 0; t < 8; t++) {
        const int lin = t * 128 + tid;           // 1024 = 64 rows * 16 groups
        const int r = lin >> 4, c4 = (lin & 15) << 2;
        float4 q4 = *(const float4*)(Qg + r * DK + c4);
        __half* dst = &Qh[r * KP + c4];
        dst[0] = __float2half_rn(q4.x * 0.125f);
        dst[1] = __float2half_rn(q4.y * 0.125f);
        dst[2] = __float2half_rn(q4.z * 0.125f);
        dst[3] = __float2half_rn(q4.w * 0.125f);
    }
    __syncthreads();

    uint32_t aq[4][4];   // Q A-fragments: 4 k16-chunks over dk=64
    {
        const int arow = w * 16 + (lane & 15);
        const int acol = ((lane >> 4) & 1) * 8;
        #pragma unroll
        for (int kc = 0; kc < 4; kc++)
            ldsm_x4(aq[kc], qBase + 2u * (arow * KP + acol + kc * 16));
    }
    // NOTE: first __syncthreads in the loop protects Qh before Kh overwrite.

    float m0v = -1e30f, m1v = -1e30f, l0v = 0.f, l1v = 0.f;
    float of[8][4];
    #pragma unroll
    for (int j = 0; j < 8; j++)
        #pragma unroll
        for (int r = 0; r < 4; r++) of[j][r] = 0.f;

    // B-fragment ldsm lane offset pieces
    const int bRow = (lane & 7) + ((lane >> 4) << 3);   // 0..15
    const int bK   = ((lane >> 3) & 1) * 8;             // 0 or 8 halves

    for (int kt = 0; kt < SS / 128; kt++) {
        __syncthreads();   // previous iter's ldsm (and Q ldsm on iter 0) done

        // ---- stage K tile [128 kpos][64 dk] fp16 ----
        const float* kp = Kg + (size_t)kt * 128 * DK;
        #pragma unroll
        for (int t = 0; t < 16; t++) {
            const int lin = t * 128 + tid;
            const int r = lin >> 4, c4 = (lin & 15) << 2;
            float4 kv = *(const float4*)(kp + r * DK + c4);
            __half* dst = &Kh[r * KP + c4];
            dst[0] = __float2half_rn(kv.x);
            dst[1] = __float2half_rn(kv.y);
            dst[2] = __float2half_rn(kv.z);
            dst[3] = __float2half_rn(kv.w);
        }
        // ---- stage V transposed: Vt[d][kpos] fp16 ----
        const float* vp = Vg + (size_t)kt * 128 * DK;
        #pragma unroll
        for (int t = 0; t < 16; t++) {
            const int lin = t * 128 + tid;
            const int d = lin & 63;
            const int kp4 = (lin >> 6) << 2;
            __half* dst = &Vt[d * VP + kp4];
            dst[0] = __float2half_rn(vp[(size_t)(kp4 + 0) * DK + d]);
            dst[1] = __float2half_rn(vp[(size_t)(kp4 + 1) * DK + d]);
            dst[2] = __float2half_rn(vp[(size_t)(kp4 + 2) * DK + d]);
            dst[3] = __float2half_rn(vp[(size_t)(kp4 + 3) * DK + d]);
        }
        __syncthreads();

        // ---- S = Q K^T : per warp 16q x 128k ----
        float sfr[16][4];
        #pragma unroll
        for (int o = 0; o < 16; o++)
            #pragma unroll
            for (int r = 0; r < 4; r++) sfr[o][r] = 0.f;

        #pragma unroll
        for (int kc = 0; kc < 4; kc++) {
            #pragma unroll
            for (int nq = 0; nq < 8; nq++) {   // n-octet pairs
                uint32_t bf[4];
                ldsm_x4(bf, kBase + 2u * ((nq * 16 + bRow) * KP + bK + kc * 16));
                mma_f16(sfr[2 * nq],     aq[kc], bf[0], bf[1]);
                mma_f16(sfr[2 * nq + 1], aq[kc], bf[2], bf[3]);
            }
        }

        // ---- mask + online softmax ----
        const int* mrow0 = Mg + (size_t)(w * 16 + g) * SS + kt * 128;
        const int* mrow1 = mrow0 + 8 * SS;
        #pragma unroll
        for (int o = 0; o < 16; o++) {
            const int2 mm0 = *(const int2*)(mrow0 + o * 8 + 2 * tig);
            const int2 mm1 = *(const int2*)(mrow1 + o * 8 + 2 * tig);
            if (mm0.x == 0) sfr[o][0] = -1e9f;
            if (mm0.y == 0) sfr[o][1] = -1e9f;
            if (mm1.x == 0) sfr[o][2] = -1e9f;
            if (mm1.y == 0) sfr[o][3] = -1e9f;
        }

        float pm0 = -1e30f, pm1 = -1e30f;
        #pragma unroll
        for (int o = 0; o < 16; o++) {
            pm0 = fmaxf(pm0, fmaxf(sfr[o][0], sfr[o][1]));
            pm1 = fmaxf(pm1, fmaxf(sfr[o][2], sfr[o][3]));
        }
        pm0 = fmaxf(pm0, __shfl_xor_sync(0xffffffffu, pm0, 1));
        pm0 = fmaxf(pm0, __shfl_xor_sync(0xffffffffu, pm0, 2));
        pm1 = fmaxf(pm1, __shfl_xor_sync(0xffffffffu, pm1, 1));
        pm1 = fmaxf(pm1, __shfl_xor_sync(0xffffffffu, pm1, 2));

        const float mn0 = fmaxf(m0v, pm0);
        const float mn1 = fmaxf(m1v, pm1);
        const float cr0 = __expf(m0v - mn0);
        const float cr1 = __expf(m1v - mn1);
        m0v = mn0; m1v = mn1;

        float rs0 = 0.f, rs1 = 0.f;
        #pragma unroll
        for (int o = 0; o < 16; o++) {
            sfr[o][0] = __expf(sfr[o][0] - mn0);
            sfr[o][1] = __expf(sfr[o][1] - mn0);
            sfr[o][2] = __expf(sfr[o][2] - mn1);
            sfr[o][3] = __expf(sfr[o][3] - mn1);
            rs0 += sfr[o][0] + sfr[o][1];
            rs1 += sfr[o][2] + sfr[o][3];
        }
        rs0 += __shfl_xor_sync(0xffffffffu, rs0, 1);
        rs0 += __shfl_xor_sync(0xffffffffu, rs0, 2);
        rs1 += __shfl_xor_sync(0xffffffffu, rs1, 1);
        rs1 += __shfl_xor_sync(0xffffffffu, rs1, 2);
        l0v = l0v * cr0 + rs0;
        l1v = l1v * cr1 + rs1;

        #pragma unroll
        for (int j = 0; j < 8; j++) {
            of[j][0] *= cr0; of[j][1] *= cr0;
            of[j][2] *= cr1; of[j][3] *= cr1;
        }

        // ---- pack P into A-fragments (in registers, no smem) ----
        uint32_t ap[8][4];
        #pragma unroll
        for (int c = 0; c < 8; c++) {
            ap[c][0] = pack_h2(sfr[2 * c][0],     sfr[2 * c][1]);
            ap[c][1] = pack_h2(sfr[2 * c][2],     sfr[2 * c][3]);
            ap[c][2] = pack_h2(sfr[2 * c + 1][0], sfr[2 * c + 1][1]);
            ap[c][3] = pack_h2(sfr[2 * c + 1][2], sfr[2 * c + 1][3]);
        }

        // ---- O += P V : per warp 16q x 64d, contraction over 128 kpos ----
        #pragma unroll
        for (int c = 0; c < 8; c++) {
            #pragma unroll
            for (int nd = 0; nd < 4; nd++) {   // d-octet pairs
                uint32_t bf[4];
                ldsm_x4(bf, vBase + 2u * ((nd * 16 + bRow) * VP + bK + c * 16));
                mma_f16(of[2 * nd],     ap[c], bf[0], bf[1]);
                mma_f16(of[2 * nd + 1], ap[c], bf[2], bf[3]);
            }
        }
    }

    // ---- epilogue: normalize, write concat[b, s, h*64 + d] ----
    const float inv0 = 1.0f / l0v;
    const float inv1 = 1.0f / l1v;
    const int row0 = q0 + w * 16 + g;
    #pragma unroll
    for (int j = 0; j < 8; j++) {
        const int col = h * DK + j * 8 + 2 * tig;
        float2 r0, r1;
        r0.x = of[j][0] * inv0; r0.y = of[j][1] * inv0;
        r1.x = of[j][2] * inv1; r1.y = of[j][3] * inv1;
        *(float2*)&outc[((size_t)(b * SS + row0)) * DM + col] = r0;
        *(float2*)&outc[((size_t)(b * SS + row0 + 8)) * DM + col] = r1;
    }
}

// ---------------------------------------------------------------------------
extern "C" void kernel_launch(void* const* d_in, const int* in_sizes, int n_in,
                              void* d_out, int out_size)
{
    const float* q    = (const float*)d_in[0];
    const float* k    = (const float*)d_in[1];
    const float* v    = (const float*)d_in[2];
    const int*   mask = (const int*)  d_in[3];
    const float* Wq   = (const float*)d_in[4];
    const float* bq   = (const float*)d_in[5];
    const float* Wk   = (const float*)d_in[6];
    const float* bk   = (const float*)d_in[7];
    const float* Wv   = (const float*)d_in[8];
    const float* bv   = (const float*)d_in[9];
    const float* Wo   = (const float*)d_in[10];
    const float* bo   = (const float*)d_in[11];
    float* out = (float*)d_out;

    float *qh, *kh, *vh, *ct;
    cudaGetSymbolAddress((void**)&qh, g_qh);
    cudaGetSymbolAddress((void**)&kh, g_kh);
    cudaGetSymbolAddress((void**)&vh, g_vh);
    cudaGetSymbolAddress((void**)&ct, g_ct);

    const dim3 gg(MROWS / 128, DM / 128);
    const dim3 bb(256);

    gemm_tf32<true><<<gg, bb>>>(q, Wq, bq, qh);
    gemm_tf32<true><<<gg, bb>>>(k, Wk, bk, kh);
    gemm_tf32<true><<<gg, bb>>>(v, Wv, bv, vh);

    cudaFuncSetAttribute(flash_f16, cudaFuncAttributeMaxDynamicSharedMemorySize,
                         FLASH_SMEM);
    flash_f16<<<dim3(SS / 64, BB * HH), 128, FLASH_SMEM>>>(mask, ct);

    gemm_tf32<false><<<gg, bb>>>(ct, Wo, bo, out);
}

// round 9
// speedup vs baseline: 5.0033x; 1.2022x over previous
#include <cuda_runtime.h>
#include <cuda_fp16.h>
#include <cstdint>

#define BB 4
#define SS 2048
#define DM 1024
#define HH 16
#define DK 64
#define MROWS (BB * SS)   // 8192

// scratch (allocation-free rule: __device__ globals)
__device__ __half   g_qh[BB * HH * SS * DK];   // pre-scaled by 0.125
__device__ __half   g_kh[BB * HH * SS * DK];
__device__ __half   g_vh[BB * HH * SS * DK];
__device__ float    g_ct[BB * SS * DM];
__device__ uint32_t g_mb[BB * SS * (SS / 32)]; // bit-packed mask (2MB)

// ---------------------------------------------------------------------------
// helpers
// ---------------------------------------------------------------------------
__device__ __forceinline__ uint32_t f2tf32(float f) {
    uint32_t u;
    asm("cvt.rna.tf32.f32 %0, %1;" : "=r"(u) : "f"(f));
    return u;
}

__device__ __forceinline__ void ldsm_x4(uint32_t* r, uint32_t addr) {
    asm volatile("ldmatrix.sync.aligned.m8n8.x4.shared.b16 {%0,%1,%2,%3}, [%4];"
                 : "=r"(r[0]), "=r"(r[1]), "=r"(r[2]), "=r"(r[3]) : "r"(addr));
}

__device__ __forceinline__ void ldsm_x4_t(uint32_t* r, uint32_t addr) {
    asm volatile("ldmatrix.sync.aligned.m8n8.x4.trans.shared.b16 {%0,%1,%2,%3}, [%4];"
                 : "=r"(r[0]), "=r"(r[1]), "=r"(r[2]), "=r"(r[3]) : "r"(addr));
}

__device__ __forceinline__ void mma_tf32(float* c, const uint32_t* a,
                                         uint32_t b0, uint32_t b1) {
    asm volatile(
        "mma.sync.aligned.m16n8k8.row.col.f32.tf32.tf32.f32 "
        "{%0,%1,%2,%3},{%4,%5,%6,%7},{%8,%9},{%0,%1,%2,%3};"
        : "+f"(c[0]), "+f"(c[1]), "+f"(c[2]), "+f"(c[3])
        : "r"(a[0]), "r"(a[1]), "r"(a[2]), "r"(a[3]), "r"(b0), "r"(b1));
}

__device__ __forceinline__ void mma_f16(float* c, const uint32_t* a,
                                        uint32_t b0, uint32_t b1) {
    asm volatile(
        "mma.sync.aligned.m16n8k16.row.col.f32.f16.f16.f32 "
        "{%0,%1,%2,%3},{%4,%5,%6,%7},{%8,%9},{%0,%1,%2,%3};"
        : "+f"(c[0]), "+f"(c[1]), "+f"(c[2]), "+f"(c[3])
        : "r"(a[0]), "r"(a[1]), "r"(a[2]), "r"(a[3]), "r"(b0), "r"(b1));
}

__device__ __forceinline__ uint32_t pack_h2(float lo, float hi) {
    __half2 h = __floats2half2_rn(lo, hi);
    return *(uint32_t*)&h;
}

__device__ __forceinline__ void cp16(uint32_t dst, const void* src) {
    asm volatile("cp.async.ca.shared.global [%0], [%1], 16;"
                 :: "r"(dst), "l"(src));
}

// ---------------------------------------------------------------------------
// mask bit-pack: one warp ballot per 32 ints
// ---------------------------------------------------------------------------
__global__ void pack_mask(const int* __restrict__ mask, uint32_t* __restrict__ mb) {
    const size_t g = (size_t)blockIdx.x * blockDim.x + threadIdx.x;
    const uint32_t word = __ballot_sync(0xffffffffu, mask[g] != 0);
    if ((threadIdx.x & 31) == 0) mb[g >> 5] = word;
}

// ---------------------------------------------------------------------------
// tf32 GEMM (round-6-validated). HEAD_OUT: writes fp16 head layout with scale.
// ---------------------------------------------------------------------------
#define GP 20

template <bool HEAD_OUT>
__global__ void __launch_bounds__(256) gemm_tf32(
    const float* __restrict__ X,
    const float* __restrict__ W,
    const float* __restrict__ bias,
    void* __restrict__ Yv,
    float scale)
{
    __shared__ uint32_t As[2][128 * GP];
    __shared__ uint32_t Bs[2][128 * GP];

    const int tid  = threadIdx.x;
    const int lane = tid & 31;
    const int warp = tid >> 5;
    const int wm   = warp >> 2;
    const int wn   = warp & 3;
    const int m0   = blockIdx.x * 128;
    const int e0   = blockIdx.y * 128;

    const int lrow = tid >> 2;
    const int lkc  = (tid & 3) << 2;

    const float* Xp = X + (size_t)(m0 + lrow) * DM + lkc;
    const float* Wp = W + (size_t)(e0 + lrow) * DM + lkc;

    float4 ra0 = *(const float4*)(Xp);
    float4 ra1 = *(const float4*)(Xp + (size_t)64 * DM);
    float4 rb0 = *(const float4*)(Wp);
    float4 rb1 = *(const float4*)(Wp + (size_t)64 * DM);

    float c[4][4][4];
    #pragma unroll
    for (int i = 0; i < 4; i++)
        #pragma unroll
        for (int j = 0; j < 4; j++)
            #pragma unroll
            for (int r = 0; r < 4; r++) c[i][j][r] = 0.f;

    const uint32_t aBase = (uint32_t)__cvta_generic_to_shared(&As[0][0]);
    const uint32_t bBase = (uint32_t)__cvta_generic_to_shared(&Bs[0][0]);
    const uint32_t bufB  = 128 * GP * 4;

    const int aOff = (wm * 64 + (lane & 15)) * GP + (((lane & 16) >> 4) << 2);
    const int bOff = (wn * 32 + (lane & 7) + ((lane & 16) >> 1)) * GP + ((lane & 8) >> 1);

    int buf = 0;
    for (int kt = 0; kt < DM / 16; kt++) {
        uint32_t* a = &As[buf][0];
        uint32_t* bsm = &Bs[buf][0];
        int o0 = lrow * GP + lkc;
        int o1 = (lrow + 64) * GP + lkc;
        a[o0 + 0] = f2tf32(ra0.x); a[o0 + 1] = f2tf32(ra0.y);
        a[o0 + 2] = f2tf32(ra0.z); a[o0 + 3] = f2tf32(ra0.w);
        a[o1 + 0] = f2tf32(ra1.x); a[o1 + 1] = f2tf32(ra1.y);
        a[o1 + 2] = f2tf32(ra1.z); a[o1 + 3] = f2tf32(ra1.w);
        bsm[o0 + 0] = f2tf32(rb0.x); bsm[o0 + 1] = f2tf32(rb0.y);
        bsm[o0 + 2] = f2tf32(rb0.z); bsm[o0 + 3] = f2tf32(rb0.w);
        bsm[o1 + 0] = f2tf32(rb1.x); bsm[o1 + 1] = f2tf32(rb1.y);
        bsm[o1 + 2] = f2tf32(rb1.z); bsm[o1 + 3] = f2tf32(rb1.w);
        __syncthreads();

        if (kt + 1 < DM / 16) {
            const float* xp = Xp + (kt + 1) * 16;
            const float* wp = Wp + (kt + 1) * 16;
            ra0 = *(const float4*)(xp);
            ra1 = *(const float4*)(xp + (size_t)64 * DM);
            rb0 = *(const float4*)(wp);
            rb1 = *(const float4*)(wp + (size_t)64 * DM);
        }

        const uint32_t ab = aBase + buf * bufB;
        const uint32_t bb = bBase + buf * bufB;
        #pragma unroll
        for (int ks = 0; ks < 16; ks += 8) {
            uint32_t afr[4][4], bfr[2][4];
            #pragma unroll
            for (int mt = 0; mt < 4; mt++)
                ldsm_x4(afr[mt], ab + 4u * (aOff + mt * 16 * GP + ks));
            #pragma unroll
            for (int np = 0; np < 2; np++)
                ldsm_x4(bfr[np], bb + 4u * (bOff + np * 16 * GP + ks));
            #pragma unroll
            for (int mt = 0; mt < 4; mt++)
                #pragma unroll
                for (int nt = 0; nt < 4; nt++)
                    mma_tf32(c[mt][nt], afr[mt],
                             bfr[nt >> 1][(nt & 1) * 2],
                             bfr[nt >> 1][(nt & 1) * 2 + 1]);
        }
        buf ^= 1;
    }
    __syncthreads();

    #pragma unroll
    for (int mt = 0; mt < 4; mt++) {
        #pragma unroll
        for (int nt = 0; nt < 4; nt++) {
            const int row = m0 + wm * 64 + mt * 16 + (lane >> 2);
            const int col = e0 + wn * 32 + nt * 8 + 2 * (lane & 3);
            const float2 bv = *(const float2*)(bias + col);
            float2 v0, v1;
            v0.x = (c[mt][nt][0] + bv.x) * scale;
            v0.y = (c[mt][nt][1] + bv.y) * scale;
            v1.x = (c[mt][nt][2] + bv.x) * scale;
            v1.y = (c[mt][nt][3] + bv.y) * scale;
            if (HEAD_OUT) {
                __half* Y = (__half*)Yv;
                const int h = col >> 6, d = col & 63;
                const int b0_ = row >> 11, s0 = row & (SS - 1);
                __half2 h0 = __floats2half2_rn(v0.x, v0.y);
                __half2 h1 = __floats2half2_rn(v1.x, v1.y);
                *(__half2*)(Y + ((size_t)((b0_ * HH + h) * SS + s0)) * DK + d) = h0;
                *(__half2*)(Y + ((size_t)((b0_ * HH + h) * SS + s0 + 8)) * DK + d) = h1;
            } else {
                float* Y = (float*)Yv;
                *(float2*)(Y + (size_t)row * DM + col) = v0;
                *(float2*)(Y + (size_t)(row + 8) * DM + col) = v1;
            }
        }
    }
}

// ---------------------------------------------------------------------------
// fp16 flash attention v2: cp.async staging, ldsm.trans for V (no transpose
// staging), register-resident Q fragments, bit-packed mask.
// CTA: 64 q-rows, KV tiles of 128, 128 threads = 4 warps (16 q-rows each).
// smem (fp16): Kh[128][KP] natural, Vh[128][KP] natural.
// ---------------------------------------------------------------------------
#define KP 72    // halves; 144B row stride -> +16B mod 128B per row, conflict-free
#define FLASH_SMEM (2 * 128 * KP * 2)   // 36864 B

__global__ void __launch_bounds__(128, 3) flash_f16(
    float* __restrict__ outc)        // [B,S,DM]
{
    extern __shared__ __half smh[];
    __half* Kh = smh;                 // [128][KP]
    __half* Vh = smh + 128 * KP;      // [128][KP]

    const int tid  = threadIdx.x;
    const int lane = tid & 31;
    const int w    = tid >> 5;        // 0..3
    const int g    = lane >> 2;       // 0..7
    const int tig  = lane & 3;        // 0..3

    const int bh = blockIdx.y;
    const int b  = bh >> 4;
    const int h  = bh & 15;
    const int q0 = blockIdx.x * 64;

    const __half* Qg = g_qh + ((size_t)bh * SS + q0) * DK;
    const __half* Kg = g_kh + (size_t)bh * SS * DK;
    const __half* Vg = g_vh + (size_t)bh * SS * DK;

    const uint32_t kBase = (uint32_t)__cvta_generic_to_shared(Kh);
    const uint32_t vBase = (uint32_t)__cvta_generic_to_shared(Vh);

    // ---- Q fragments straight from global (m16n8k16 A layout) ----
    uint32_t aq[4][4];
    {
        const __half* qr0 = Qg + (size_t)(w * 16 + g) * DK + 2 * tig;
        const __half* qr1 = qr0 + 8 * DK;
        #pragma unroll
        for (int kc = 0; kc < 4; kc++) {
            aq[kc][0] = *(const uint32_t*)(qr0 + kc * 16);
            aq[kc][1] = *(const uint32_t*)(qr1 + kc * 16);
            aq[kc][2] = *(const uint32_t*)(qr0 + kc * 16 + 8);
            aq[kc][3] = *(const uint32_t*)(qr1 + kc * 16 + 8);
        }
    }

    // mask bit rows
    const uint32_t* MBr0 = g_mb + ((size_t)b * SS + q0 + w * 16 + g) * (SS / 32);
    const uint32_t* MBr1 = MBr0 + 8 * (SS / 32);

    float m0v = -1e30f, m1v = -1e30f, l0v = 0.f, l1v = 0.f;
    float of[8][4];
    #pragma unroll
    for (int j = 0; j < 8; j++)
        #pragma unroll
        for (int r = 0; r < 4; r++) of[j][r] = 0.f;

    // ldsm lane offsets
    const int bRow = (lane & 7) + ((lane >> 4) << 3);   // K (non-trans B): 0..15
    const int bK   = ((lane >> 3) & 1) * 8;             // 0 or 8 halves
    const int vTile = lane >> 3;                        // trans: tile id 0..3
    const int vR    = lane & 7;                         // row in tile

    for (int kt = 0; kt < SS / 128; kt++) {
        __syncthreads();   // previous iter's ldsm reads done

        // ---- stage K & V tiles via cp.async (16B each) ----
        const __half* kp = Kg + (size_t)kt * 128 * DK;
        const __half* vp = Vg + (size_t)kt * 128 * DK;
        #pragma unroll
        for (int t = 0; t < 8; t++) {
            const int lin = t * 128 + tid;     // 1024 groups
            const int r = lin >> 3, grp8 = (lin & 7) << 3;
            cp16(kBase + 2u * (r * KP + grp8), kp + (size_t)r * DK + grp8);
            cp16(vBase + 2u * (r * KP + grp8), vp + (size_t)r * DK + grp8);
        }
        asm volatile("cp.async.commit_group;");
        asm volatile("cp.async.wait_group 0;");
        __syncthreads();

        // ---- S = Q K^T : per warp 16q x 128k ----
        float sfr[16][4];
        #pragma unroll
        for (int o = 0; o < 16; o++)
            #pragma unroll
            for (int r = 0; r < 4; r++) sfr[o][r] = 0.f;

        #pragma unroll
        for (int kc = 0; kc < 4; kc++) {
            #pragma unroll
            for (int nq = 0; nq < 8; nq++) {
                uint32_t bf[4];
                ldsm_x4(bf, kBase + 2u * ((nq * 16 + bRow) * KP + bK + kc * 16));
                mma_f16(sfr[2 * nq],     aq[kc], bf[0], bf[1]);
                mma_f16(sfr[2 * nq + 1], aq[kc], bf[2], bf[3]);
            }
        }

        // ---- bit-packed mask ----
        const uint4 mw0 = *(const uint4*)(MBr0 + kt * 4);
        const uint4 mw1 = *(const uint4*)(MBr1 + kt * 4);
        const uint32_t allw = mw0.x & mw0.y & mw0.z & mw0.w &
                              mw1.x & mw1.y & mw1.z & mw1.w;
        if (allw != 0xffffffffu) {
            #pragma unroll
            for (int o = 0; o < 16; o++) {
                const uint32_t wd0 = (o < 4) ? mw0.x : (o < 8) ? mw0.y
                                   : (o < 12) ? mw0.z : mw0.w;
                const uint32_t wd1 = (o < 4) ? mw1.x : (o < 8) ? mw1.y
                                   : (o < 12) ? mw1.z : mw1.w;
                const int bit = (o & 3) * 8 + 2 * tig;
                if (!((wd0 >> bit) & 1))       sfr[o][0] = -1e9f;
                if (!((wd0 >> (bit + 1)) & 1)) sfr[o][1] = -1e9f;
                if (!((wd1 >> bit) & 1))       sfr[o][2] = -1e9f;
                if (!((wd1 >> (bit + 1)) & 1)) sfr[o][3] = -1e9f;
            }
        }

        // ---- online softmax ----
        float pm0 = -1e30f, pm1 = -1e30f;
        #pragma unroll
        for (int o = 0; o < 16; o++) {
            pm0 = fmaxf(pm0, fmaxf(sfr[o][0], sfr[o][1]));
            pm1 = fmaxf(pm1, fmaxf(sfr[o][2], sfr[o][3]));
        }
        pm0 = fmaxf(pm0, __shfl_xor_sync(0xffffffffu, pm0, 1));
        pm0 = fmaxf(pm0, __shfl_xor_sync(0xffffffffu, pm0, 2));
        pm1 = fmaxf(pm1, __shfl_xor_sync(0xffffffffu, pm1, 1));
        pm1 = fmaxf(pm1, __shfl_xor_sync(0xffffffffu, pm1, 2));

        const float mn0 = fmaxf(m0v, pm0);
        const float mn1 = fmaxf(m1v, pm1);
        const float cr0 = __expf(m0v - mn0);
        const float cr1 = __expf(m1v - mn1);
        m0v = mn0; m1v = mn1;

        float rs0 = 0.f, rs1 = 0.f;
        #pragma unroll
        for (int o = 0; o < 16; o++) {
            sfr[o][0] = __expf(sfr[o][0] - mn0);
            sfr[o][1] = __expf(sfr[o][1] - mn0);
            sfr[o][2] = __expf(sfr[o][2] - mn1);
            sfr[o][3] = __expf(sfr[o][3] - mn1);
            rs0 += sfr[o][0] + sfr[o][1];
            rs1 += sfr[o][2] + sfr[o][3];
        }
        rs0 += __shfl_xor_sync(0xffffffffu, rs0, 1);
        rs0 += __shfl_xor_sync(0xffffffffu, rs0, 2);
        rs1 += __shfl_xor_sync(0xffffffffu, rs1, 1);
        rs1 += __shfl_xor_sync(0xffffffffu, rs1, 2);
        l0v = l0v * cr0 + rs0;
        l1v = l1v * cr1 + rs1;

        #pragma unroll
        for (int j = 0; j < 8; j++) {
            of[j][0] *= cr0; of[j][1] *= cr0;
            of[j][2] *= cr1; of[j][3] *= cr1;
        }

        // ---- pack P into A-fragments (registers only) ----
        uint32_t ap[8][4];
        #pragma unroll
        for (int c = 0; c < 8; c++) {
            ap[c][0] = pack_h2(sfr[2 * c][0],     sfr[2 * c][1]);
            ap[c][1] = pack_h2(sfr[2 * c][2],     sfr[2 * c][3]);
            ap[c][2] = pack_h2(sfr[2 * c + 1][0], sfr[2 * c + 1][1]);
            ap[c][3] = pack_h2(sfr[2 * c + 1][2], sfr[2 * c + 1][3]);
        }

        // ---- O += P V : ldsm.trans from natural V [kpos][dk] ----
        #pragma unroll
        for (int c = 0; c < 8; c++) {          // k16 chunk over kpos
            #pragma unroll
            for (int nd = 0; nd < 4; nd++) {   // d16 chunk
                // trans tiles: (tile&1) -> kpos octet, (tile>>1) -> d octet
                uint32_t bf[4];
                const int krow = c * 16 + (vTile & 1) * 8 + vR;
                const int dcol = nd * 16 + (vTile >> 1) * 8;
                ldsm_x4_t(bf, vBase + 2u * (krow * KP + dcol));
                mma_f16(of[2 * nd],     ap[c], bf[0], bf[1]);
                mma_f16(of[2 * nd + 1], ap[c], bf[2], bf[3]);
            }
        }
    }

    // ---- epilogue: normalize, write concat[b, s, h*64 + d] (fp32) ----
    const float inv0 = 1.0f / l0v;
    const float inv1 = 1.0f / l1v;
    const int row0 = q0 + w * 16 + g;
    #pragma unroll
    for (int j = 0; j < 8; j++) {
        const int col = h * DK + j * 8 + 2 * tig;
        float2 r0, r1;
        r0.x = of[j][0] * inv0; r0.y = of[j][1] * inv0;
        r1.x = of[j][2] * inv1; r1.y = of[j][3] * inv1;
        *(float2*)&outc[((size_t)(b * SS + row0)) * DM + col] = r0;
        *(float2*)&outc[((size_t)(b * SS + row0 + 8)) * DM + col] = r1;
    }
}

// ---------------------------------------------------------------------------
extern "C" void kernel_launch(void* const* d_in, const int* in_sizes, int n_in,
                              void* d_out, int out_size)
{
    const float* q    = (const float*)d_in[0];
    const float* k    = (const float*)d_in[1];
    const float* v    = (const float*)d_in[2];
    const int*   mask = (const int*)  d_in[3];
    const float* Wq   = (const float*)d_in[4];
    const float* bq   = (const float*)d_in[5];
    const float* Wk   = (const float*)d_in[6];
    const float* bk   = (const float*)d_in[7];
    const float* Wv   = (const float*)d_in[8];
    const float* bv   = (const float*)d_in[9];
    const float* Wo   = (const float*)d_in[10];
    const float* bo   = (const float*)d_in[11];
    float* out = (float*)d_out;

    __half *qh, *kh, *vh;
    float *ct;
    uint32_t* mb;
    cudaGetSymbolAddress((void**)&qh, g_qh);
    cudaGetSymbolAddress((void**)&kh, g_kh);
    cudaGetSymbolAddress((void**)&vh, g_vh);
    cudaGetSymbolAddress((void**)&ct, g_ct);
    cudaGetSymbolAddress((void**)&mb, g_mb);

    const dim3 gg(MROWS / 128, DM / 128);
    const dim3 bb(256);

    pack_mask<<<(BB * SS * SS) / 256, 256>>>(mask, mb);

    gemm_tf32<true><<<gg, bb>>>(q, Wq, bq, qh, 0.125f);
    gemm_tf32<true><<<gg, bb>>>(k, Wk, bk, kh, 1.0f);
    gemm_tf32<true><<<gg, bb>>>(v, Wv, bv, vh, 1.0f);

    cudaFuncSetAttribute(flash_f16, cudaFuncAttributeMaxDynamicSharedMemorySize,
                         FLASH_SMEM);
    flash_f16<<<dim3(SS / 64, BB * HH), 128, FLASH_SMEM>>>(ct);

    gemm_tf32<false><<<gg, bb>>>(ct, Wo, bo, out, 1.0f);
}

// round 10
// speedup vs baseline: 7.3321x; 1.4655x over previous
#include <cuda_runtime.h>
#include <cuda_fp16.h>
#include <cstdint>

#define BB 4
#define SS 2048
#define DM 1024
#define HH 16
#define DK 64
#define MROWS (BB * SS)   // 8192

// scratch (allocation-free rule: __device__ globals)
__device__ __half   g_qh[BB * HH * SS * DK];   // pre-scaled by 0.125
__device__ __half   g_kh[BB * HH * SS * DK];
__device__ __half   g_vh[BB * HH * SS * DK];
__device__ __half   g_ct[BB * SS * DM];        // fp16 concat
__device__ __half   g_xh[MROWS * DM];          // fp16 staging of q/k/v
__device__ __half   g_wh[DM * DM];             // fp16 staging of W*
__device__ uint32_t g_mb[BB * SS * (SS / 32)]; // bit-packed mask (2MB)

// ---------------------------------------------------------------------------
// helpers
// ---------------------------------------------------------------------------
__device__ __forceinline__ void ldsm_x4(uint32_t* r, uint32_t addr) {
    asm volatile("ldmatrix.sync.aligned.m8n8.x4.shared.b16 {%0,%1,%2,%3}, [%4];"
                 : "=r"(r[0]), "=r"(r[1]), "=r"(r[2]), "=r"(r[3]) : "r"(addr));
}

__device__ __forceinline__ void ldsm_x4_t(uint32_t* r, uint32_t addr) {
    asm volatile("ldmatrix.sync.aligned.m8n8.x4.trans.shared.b16 {%0,%1,%2,%3}, [%4];"
                 : "=r"(r[0]), "=r"(r[1]), "=r"(r[2]), "=r"(r[3]) : "r"(addr));
}

__device__ __forceinline__ void mma_f16(float* c, const uint32_t* a,
                                        uint32_t b0, uint32_t b1) {
    asm volatile(
        "mma.sync.aligned.m16n8k16.row.col.f32.f16.f16.f32 "
        "{%0,%1,%2,%3},{%4,%5,%6,%7},{%8,%9},{%0,%1,%2,%3};"
        : "+f"(c[0]), "+f"(c[1]), "+f"(c[2]), "+f"(c[3])
        : "r"(a[0]), "r"(a[1]), "r"(a[2]), "r"(a[3]), "r"(b0), "r"(b1));
}

__device__ __forceinline__ uint32_t pack_h2(float lo, float hi) {
    __half2 h = __floats2half2_rn(lo, hi);
    return *(uint32_t*)&h;
}

__device__ __forceinline__ void cp16(uint32_t dst, const void* src) {
    asm volatile("cp.async.ca.shared.global [%0], [%1], 16;"
                 :: "r"(dst), "l"(src));
}

// ---------------------------------------------------------------------------
// fp32 -> fp16 elementwise (8 elems/thread)
// ---------------------------------------------------------------------------
__global__ void f32_to_f16(const float* __restrict__ src,
                           __half* __restrict__ dst) {
    const size_t i = ((size_t)blockIdx.x * blockDim.x + threadIdx.x) * 8;
    const float4 a = *(const float4*)(src + i);
    const float4 b = *(const float4*)(src + i + 4);
    __half2 h[4];
    h[0] = __floats2half2_rn(a.x, a.y);
    h[1] = __floats2half2_rn(a.z, a.w);
    h[2] = __floats2half2_rn(b.x, b.y);
    h[3] = __floats2half2_rn(b.z, b.w);
    *(uint4*)(dst + i) = *(const uint4*)h;
}

// ---------------------------------------------------------------------------
// mask bit-pack: one warp ballot per 32 ints
// ---------------------------------------------------------------------------
__global__ void pack_mask(const int* __restrict__ mask, uint32_t* __restrict__ mb) {
    const size_t g = (size_t)blockIdx.x * blockDim.x + threadIdx.x;
    const uint32_t word = __ballot_sync(0xffffffffu, mask[g] != 0);
    if ((threadIdx.x & 31) == 0) mb[g >> 5] = word;
}

// ---------------------------------------------------------------------------
// fp16 GEMM:  Y[m,e] = sum_d X[m,d] * W[e,d] + bias[e]
// 128x128x32 CTA tile, 256 threads (8 warps 2x4), m16n8k16, cp.async
// double-buffered. KPH=40 halves (80B rows -> conflict-free ldsm).
// ---------------------------------------------------------------------------
#define KPH 40

template <bool HEAD_OUT>
__global__ void __launch_bounds__(256, 2) gemm_f16(
    const __half* __restrict__ X,     // [MROWS, DM] fp16
    const __half* __restrict__ W,     // [DM(e), DM(d)] fp16
    const float* __restrict__ bias,   // [DM]
    void* __restrict__ Yv,
    float scale)
{
    __shared__ __half Ah[2][128 * KPH];
    __shared__ __half Bh[2][128 * KPH];

    const int tid  = threadIdx.x;
    const int lane = tid & 31;
    const int warp = tid >> 5;
    const int wm   = warp >> 2;          // 0..1 (64 rows)
    const int wn   = warp & 3;           // 0..3 (32 cols)
    const int m0   = blockIdx.x * 128;
    const int e0   = blockIdx.y * 128;

    const uint32_t aBase = (uint32_t)__cvta_generic_to_shared(&Ah[0][0]);
    const uint32_t bBase = (uint32_t)__cvta_generic_to_shared(&Bh[0][0]);
    const uint32_t bufB  = 128 * KPH * 2;   // bytes per buffer

    // loader mapping: 512 chunks of 16B per matrix per K-step; 2 per thread
    // lin = t*256+tid: r = lin>>2 (0..127), c8 = (lin&3)*8 halves
    const __half* Xp = X + (size_t)m0 * DM;
    const __half* Wp = W + (size_t)e0 * DM;

    float c[4][4][4];
    #pragma unroll
    for (int i = 0; i < 4; i++)
        #pragma unroll
        for (int j = 0; j < 4; j++)
            #pragma unroll
            for (int r = 0; r < 4; r++) c[i][j][r] = 0.f;

    // ldsm lane offsets (validated in flash kernel)
    const int aRow = (lane & 15);
    const int aCol = ((lane >> 4) & 1) * 8;
    const int bRow = (lane & 7) + ((lane >> 4) << 3);
    const int bK   = ((lane >> 3) & 1) * 8;

    // ---- preload K-step 0 ----
    {
        #pragma unroll
        for (int t = 0; t < 2; t++) {
            const int lin = t * 256 + tid;
            const int r = lin >> 2, c8 = (lin & 3) << 3;
            cp16(aBase + 2u * (r * KPH + c8), Xp + (size_t)r * DM + c8);
            cp16(bBase + 2u * (r * KPH + c8), Wp + (size_t)r * DM + c8);
        }
        asm volatile("cp.async.commit_group;");
    }

    int buf = 0;
    for (int kt = 0; kt < DM / 32; kt++) {
        asm volatile("cp.async.wait_group 0;");
        __syncthreads();   // tile kt ready; all warps done with buf^1

        if (kt + 1 < DM / 32) {
            const int k0 = (kt + 1) * 32;
            const uint32_t ao = aBase + (buf ^ 1) * bufB;
            const uint32_t bo = bBase + (buf ^ 1) * bufB;
            #pragma unroll
            for (int t = 0; t < 2; t++) {
                const int lin = t * 256 + tid;
                const int r = lin >> 2, c8 = (lin & 3) << 3;
                cp16(ao + 2u * (r * KPH + c8), Xp + (size_t)r * DM + k0 + c8);
                cp16(bo + 2u * (r * KPH + c8), Wp + (size_t)r * DM + k0 + c8);
            }
            asm volatile("cp.async.commit_group;");
        }

        const uint32_t ab = aBase + buf * bufB;
        const uint32_t bb = bBase + buf * bufB;
        #pragma unroll
        for (int kc = 0; kc < 2; kc++) {
            uint32_t afr[4][4], bfr[2][4];
            #pragma unroll
            for (int mt = 0; mt < 4; mt++)
                ldsm_x4(afr[mt], ab + 2u * ((wm * 64 + mt * 16 + aRow) * KPH
                                            + aCol + kc * 16));
            #pragma unroll
            for (int nq = 0; nq < 2; nq++)
                ldsm_x4(bfr[nq], bb + 2u * ((wn * 32 + nq * 16 + bRow) * KPH
                                            + bK + kc * 16));
            #pragma unroll
            for (int mt = 0; mt < 4; mt++)
                #pragma unroll
                for (int nt = 0; nt < 4; nt++)
                    mma_f16(c[mt][nt], afr[mt],
                            bfr[nt >> 1][(nt & 1) * 2],
                            bfr[nt >> 1][(nt & 1) * 2 + 1]);
        }
        buf ^= 1;
    }

    // epilogue (same C-fragment layout as tf32 version)
    #pragma unroll
    for (int mt = 0; mt < 4; mt++) {
        #pragma unroll
        for (int nt = 0; nt < 4; nt++) {
            const int row = m0 + wm * 64 + mt * 16 + (lane >> 2);
            const int col = e0 + wn * 32 + nt * 8 + 2 * (lane & 3);
            const float2 bv = *(const float2*)(bias + col);
            float2 v0, v1;
            v0.x = (c[mt][nt][0] + bv.x) * scale;
            v0.y = (c[mt][nt][1] + bv.y) * scale;
            v1.x = (c[mt][nt][2] + bv.x) * scale;
            v1.y = (c[mt][nt][3] + bv.y) * scale;
            if (HEAD_OUT) {
                __half* Y = (__half*)Yv;
                const int h = col >> 6, d = col & 63;
                const int b0_ = row >> 11, s0 = row & (SS - 1);
                __half2 h0 = __floats2half2_rn(v0.x, v0.y);
                __half2 h1 = __floats2half2_rn(v1.x, v1.y);
                *(__half2*)(Y + ((size_t)((b0_ * HH + h) * SS + s0)) * DK + d) = h0;
                *(__half2*)(Y + ((size_t)((b0_ * HH + h) * SS + s0 + 8)) * DK + d) = h1;
            } else {
                float* Y = (float*)Yv;
                *(float2*)(Y + (size_t)row * DM + col) = v0;
                *(float2*)(Y + (size_t)(row + 8) * DM + col) = v1;
            }
        }
    }
}

// ---------------------------------------------------------------------------
// fp16 flash attention (round-9-validated), epilogue now writes fp16 ct.
// ---------------------------------------------------------------------------
#define KP 72
#define FLASH_SMEM (2 * 128 * KP * 2)   // 36864 B

__global__ void __launch_bounds__(128, 3) flash_f16(
    __half* __restrict__ outc)        // [B,S,DM] fp16
{
    extern __shared__ __half smh[];
    __half* Kh = smh;
    __half* Vh = smh + 128 * KP;

    const int tid  = threadIdx.x;
    const int lane = tid & 31;
    const int w    = tid >> 5;
    const int g    = lane >> 2;
    const int tig  = lane & 3;

    const int bh = blockIdx.y;
    const int b  = bh >> 4;
    const int h  = bh & 15;
    const int q0 = blockIdx.x * 64;

    const __half* Qg = g_qh + ((size_t)bh * SS + q0) * DK;
    const __half* Kg = g_kh + (size_t)bh * SS * DK;
    const __half* Vg = g_vh + (size_t)bh * SS * DK;

    const uint32_t kBase = (uint32_t)__cvta_generic_to_shared(Kh);
    const uint32_t vBase = (uint32_t)__cvta_generic_to_shared(Vh);

    uint32_t aq[4][4];
    {
        const __half* qr0 = Qg + (size_t)(w * 16 + g) * DK + 2 * tig;
        const __half* qr1 = qr0 + 8 * DK;
        #pragma unroll
        for (int kc = 0; kc < 4; kc++) {
            aq[kc][0] = *(const uint32_t*)(qr0 + kc * 16);
            aq[kc][1] = *(const uint32_t*)(qr1 + kc * 16);
            aq[kc][2] = *(const uint32_t*)(qr0 + kc * 16 + 8);
            aq[kc][3] = *(const uint32_t*)(qr1 + kc * 16 + 8);
        }
    }

    const uint32_t* MBr0 = g_mb + ((size_t)b * SS + q0 + w * 16 + g) * (SS / 32);
    const uint32_t* MBr1 = MBr0 + 8 * (SS / 32);

    float m0v = -1e30f, m1v = -1e30f, l0v = 0.f, l1v = 0.f;
    float of[8][4];
    #pragma unroll
    for (int j = 0; j < 8; j++)
        #pragma unroll
        for (int r = 0; r < 4; r++) of[j][r] = 0.f;

    const int bRow = (lane & 7) + ((lane >> 4) << 3);
    const int bK   = ((lane >> 3) & 1) * 8;
    const int vTile = lane >> 3;
    const int vR    = lane & 7;

    for (int kt = 0; kt < SS / 128; kt++) {
        __syncthreads();

        const __half* kp = Kg + (size_t)kt * 128 * DK;
        const __half* vp = Vg + (size_t)kt * 128 * DK;
        #pragma unroll
        for (int t = 0; t < 8; t++) {
            const int lin = t * 128 + tid;
            const int r = lin >> 3, grp8 = (lin & 7) << 3;
            cp16(kBase + 2u * (r * KP + grp8), kp + (size_t)r * DK + grp8);
            cp16(vBase + 2u * (r * KP + grp8), vp + (size_t)r * DK + grp8);
        }
        asm volatile("cp.async.commit_group;");
        asm volatile("cp.async.wait_group 0;");
        __syncthreads();

        float sfr[16][4];
        #pragma unroll
        for (int o = 0; o < 16; o++)
            #pragma unroll
            for (int r = 0; r < 4; r++) sfr[o][r] = 0.f;

        #pragma unroll
        for (int kc = 0; kc < 4; kc++) {
            #pragma unroll
            for (int nq = 0; nq < 8; nq++) {
                uint32_t bf[4];
                ldsm_x4(bf, kBase + 2u * ((nq * 16 + bRow) * KP + bK + kc * 16));
                mma_f16(sfr[2 * nq],     aq[kc], bf[0], bf[1]);
                mma_f16(sfr[2 * nq + 1], aq[kc], bf[2], bf[3]);
            }
        }

        const uint4 mw0 = *(const uint4*)(MBr0 + kt * 4);
        const uint4 mw1 = *(const uint4*)(MBr1 + kt * 4);
        const uint32_t allw = mw0.x & mw0.y & mw0.z & mw0.w &
                              mw1.x & mw1.y & mw1.z & mw1.w;
        if (allw != 0xffffffffu) {
            #pragma unroll
            for (int o = 0; o < 16; o++) {
                const uint32_t wd0 = (o < 4) ? mw0.x : (o < 8) ? mw0.y
                                   : (o < 12) ? mw0.z : mw0.w;
                const uint32_t wd1 = (o < 4) ? mw1.x : (o < 8) ? mw1.y
                                   : (o < 12) ? mw1.z : mw1.w;
                const int bit = (o & 3) * 8 + 2 * tig;
                if (!((wd0 >> bit) & 1))       sfr[o][0] = -1e9f;
                if (!((wd0 >> (bit + 1)) & 1)) sfr[o][1] = -1e9f;
                if (!((wd1 >> bit) & 1))       sfr[o][2] = -1e9f;
                if (!((wd1 >> (bit + 1)) & 1)) sfr[o][3] = -1e9f;
            }
        }

        float pm0 = -1e30f, pm1 = -1e30f;
        #pragma unroll
        for (int o = 0; o < 16; o++) {
            pm0 = fmaxf(pm0, fmaxf(sfr[o][0], sfr[o][1]));
            pm1 = fmaxf(pm1, fmaxf(sfr[o][2], sfr[o][3]));
        }
        pm0 = fmaxf(pm0, __shfl_xor_sync(0xffffffffu, pm0, 1));
        pm0 = fmaxf(pm0, __shfl_xor_sync(0xffffffffu, pm0, 2));
        pm1 = fmaxf(pm1, __shfl_xor_sync(0xffffffffu, pm1, 1));
        pm1 = fmaxf(pm1, __shfl_xor_sync(0xffffffffu, pm1, 2));

        const float mn0 = fmaxf(m0v, pm0);
        const float mn1 = fmaxf(m1v, pm1);
        const float cr0 = __expf(m0v - mn0);
        const float cr1 = __expf(m1v - mn1);
        m0v = mn0; m1v = mn1;

        float rs0 = 0.f, rs1 = 0.f;
        #pragma unroll
        for (int o = 0; o < 16; o++) {
            sfr[o][0] = __expf(sfr[o][0] - mn0);
            sfr[o][1] = __expf(sfr[o][1] - mn0);
            sfr[o][2] = __expf(sfr[o][2] - mn1);
            sfr[o][3] = __expf(sfr[o][3] - mn1);
            rs0 += sfr[o][0] + sfr[o][1];
            rs1 += sfr[o][2] + sfr[o][3];
        }
        rs0 += __shfl_xor_sync(0xffffffffu, rs0, 1);
        rs0 += __shfl_xor_sync(0xffffffffu, rs0, 2);
        rs1 += __shfl_xor_sync(0xffffffffu, rs1, 1);
        rs1 += __shfl_xor_sync(0xffffffffu, rs1, 2);
        l0v = l0v * cr0 + rs0;
        l1v = l1v * cr1 + rs1;

        #pragma unroll
        for (int j = 0; j < 8; j++) {
            of[j][0] *= cr0; of[j][1] *= cr0;
            of[j][2] *= cr1; of[j][3] *= cr1;
        }

        uint32_t ap[8][4];
        #pragma unroll
        for (int c = 0; c < 8; c++) {
            ap[c][0] = pack_h2(sfr[2 * c][0],     sfr[2 * c][1]);
            ap[c][1] = pack_h2(sfr[2 * c][2],     sfr[2 * c][3]);
            ap[c][2] = pack_h2(sfr[2 * c + 1][0], sfr[2 * c + 1][1]);
            ap[c][3] = pack_h2(sfr[2 * c + 1][2], sfr[2 * c + 1][3]);
        }

        #pragma unroll
        for (int c = 0; c < 8; c++) {
            #pragma unroll
            for (int nd = 0; nd < 4; nd++) {
                uint32_t bf[4];
                const int krow = c * 16 + (vTile & 1) * 8 + vR;
                const int dcol = nd * 16 + (vTile >> 1) * 8;
                ldsm_x4_t(bf, vBase + 2u * (krow * KP + dcol));
                mma_f16(of[2 * nd],     ap[c], bf[0], bf[1]);
                mma_f16(of[2 * nd + 1], ap[c], bf[2], bf[3]);
            }
        }
    }

    // epilogue: normalize, write fp16 concat[b, s, h*64 + d]
    const float inv0 = 1.0f / l0v;
    const float inv1 = 1.0f / l1v;
    const int row0 = q0 + w * 16 + g;
    #pragma unroll
    for (int j = 0; j < 8; j++) {
        const int col = h * DK + j * 8 + 2 * tig;
        __half2 h0 = __floats2half2_rn(of[j][0] * inv0, of[j][1] * inv0);
        __half2 h1 = __floats2half2_rn(of[j][2] * inv1, of[j][3] * inv1);
        *(__half2*)&outc[((size_t)(b * SS + row0)) * DM + col] = h0;
        *(__half2*)&outc[((size_t)(b * SS + row0 + 8)) * DM + col] = h1;
    }
}

// ---------------------------------------------------------------------------
extern "C" void kernel_launch(void* const* d_in, const int* in_sizes, int n_in,
                              void* d_out, int out_size)
{
    const float* q    = (const float*)d_in[0];
    const float* k    = (const float*)d_in[1];
    const float* v    = (const float*)d_in[2];
    const int*   mask = (const int*)  d_in[3];
    const float* Wq   = (const float*)d_in[4];
    const float* bq   = (const float*)d_in[5];
    const float* Wk   = (const float*)d_in[6];
    const float* bk   = (const float*)d_in[7];
    const float* Wv   = (const float*)d_in[8];
    const float* bv   = (const float*)d_in[9];
    const float* Wo   = (const float*)d_in[10];
    const float* bo   = (const float*)d_in[11];
    float* out = (float*)d_out;

    __half *qh, *kh, *vh, *ct, *xh, *wh;
    uint32_t* mb;
    cudaGetSymbolAddress((void**)&qh, g_qh);
    cudaGetSymbolAddress((void**)&kh, g_kh);
    cudaGetSymbolAddress((void**)&vh, g_vh);
    cudaGetSymbolAddress((void**)&ct, g_ct);
    cudaGetSymbolAddress((void**)&xh, g_xh);
    cudaGetSymbolAddress((void**)&wh, g_wh);
    cudaGetSymbolAddress((void**)&mb, g_mb);

    const dim3 gg(MROWS / 128, DM / 128);
    const dim3 bb(256);
    const int XCONV_BLOCKS = (MROWS * DM) / (256 * 8);   // 4096
    const int WCONV_BLOCKS = (DM * DM) / (256 * 8);      // 512

    pack_mask<<<(BB * SS * SS) / 256, 256>>>(mask, mb);

    // Q projection
    f32_to_f16<<<XCONV_BLOCKS, 256>>>(q, xh);
    f32_to_f16<<<WCONV_BLOCKS, 256>>>(Wq, wh);
    gemm_f16<true><<<gg, bb>>>(xh, wh, bq, qh, 0.125f);
    // K projection
    f32_to_f16<<<XCONV_BLOCKS, 256>>>(k, xh);
    f32_to_f16<<<WCONV_BLOCKS, 256>>>(Wk, wh);
    gemm_f16<true><<<gg, bb>>>(xh, wh, bk, kh, 1.0f);
    // V projection
    f32_to_f16<<<XCONV_BLOCKS, 256>>>(v, xh);
    f32_to_f16<<<WCONV_BLOCKS, 256>>>(Wv, wh);
    gemm_f16<true><<<gg, bb>>>(xh, wh, bv, vh, 1.0f);

    cudaFuncSetAttribute(flash_f16, cudaFuncAttributeMaxDynamicSharedMemorySize,
                         FLASH_SMEM);
    flash_f16<<<dim3(SS / 64, BB * HH), 128, FLASH_SMEM>>>(ct);

    // output projection (ct already fp16)
    f32_to_f16<<<WCONV_BLOCKS, 256>>>(Wo, wh);
    gemm_f16<false><<<gg, bb>>>(ct, wh, bo, out, 1.0f);
}